// round 8
// baseline (speedup 1.0000x reference)
#include <cuda_runtime.h>

#define TT    8192
#define SEG   2048
#define NTH   256
#define CH    8
#define NW    (NTH/32)
#define FEPS  1e-8f

#define HALO1 256
#define TOT1  (SEG + HALO1)        // 2304
#define CHS   9                    // TOT1/NTH
#define SC1   (TOT1 + TOT1/32)     // 2376

__device__ __forceinline__ int PADI(int i){ return i + (i >> 5); }
__device__ __forceinline__ float sum4(float4 v){ return (v.x + v.y) + (v.z + v.w); }

__device__ __forceinline__ void wscan(float& c, float& d, int lane){
    #pragma unroll
    for (int off = 1; off < 32; off <<= 1) {
        float pc = __shfl_up_sync(0xffffffffu, c, off);
        float pd = __shfl_up_sync(0xffffffffu, d, off);
        if (lane >= off) { d = fmaf(pd, c, d); c *= pc; }
    }
}

// ======================= K1: EMA features 9,10,11 =======================
extern "C" __global__ void __launch_bounds__(NTH, 6)
ema_kernel(const float* __restrict__ gclose, float* __restrict__ gout, size_t BT)
{
    __shared__ float sc[SC1];
    __shared__ float swp[3 * NW];
    __shared__ float si[3 * NTH];

    const int blk  = blockIdx.x;
    const int row  = blk >> 2;
    const int seg  = blk & 3;
    const int tid  = threadIdx.x;
    const int lane = tid & 31;
    const int wid  = tid >> 5;
    const float* x = gclose + (size_t)row * TT;
    const int basem = seg * SEG;

    {
        const float x0 = x[0];
        #pragma unroll
        for (int j = 0; j < 3; ++j) {
            int i4 = tid + j * NTH;
            if (i4 < TOT1 / 4) {
                int gi = basem - HALO1 + i4 * 4;
                float4 v = (gi >= 0) ? *(const float4*)(x + gi)
                                     : make_float4(x0, x0, x0, x0);
                int b = i4 * 4;
                sc[PADI(b)]     = v.x;
                sc[PADI(b + 1)] = v.y;
                sc[PADI(b + 2)] = v.z;
                sc[PADI(b + 3)] = v.w;
            }
        }
    }
    __syncthreads();

    const float aF = 2.0f / 13.0f, omF = 1.0f - aF;
    const float aS = 2.0f / 27.0f, omS = 1.0f - aS;
    const float aG = 0.2f,         omG = 0.8f;

    const int i0 = HALO1 + CH * tid;
    float* ob = gout + (size_t)row * TT + basem + CH * tid;

    float yF0, yS0;
    {
        const int s0 = tid * CHS;
        float cF = 1.f, dF = 0.f, cS = 1.f, dS = 0.f;
        #pragma unroll
        for (int k = 0; k < CHS; ++k) {
            float v = sc[PADI(s0 + k)];
            dF = fmaf(aF, v, omF * dF); cF *= omF;
            dS = fmaf(aS, v, omS * dS); cS *= omS;
        }
        wscan(cF, dF, lane);
        wscan(cS, dS, lane);
        if (lane == 31) { swp[wid] = dF; swp[NW + wid] = dS; }
        float uF  = __shfl_up_sync(0xffffffffu, dF, 1);
        float ucF = __shfl_up_sync(0xffffffffu, cF, 1);
        float uS  = __shfl_up_sync(0xffffffffu, dS, 1);
        float ucS = __shfl_up_sync(0xffffffffu, cS, 1);
        __syncthreads();
        float pF = (wid > 0) ? swp[wid - 1]      : 0.f;
        float pS = (wid > 0) ? swp[NW + wid - 1] : 0.f;
        yF0 = (lane == 0) ? pF : fmaf(ucF, pF, uF);
        yS0 = (lane == 0) ? pS : fmaf(ucS, pS, uS);
    }

    float y90;
    {
        const int s0 = tid * CHS;
        float yF = yF0, yS = yS0, cG = 1.f, dG = 0.f;
        #pragma unroll
        for (int k = 0; k < CHS; ++k) {
            float v = sc[PADI(s0 + k)];
            yF = fmaf(aF, v, omF * yF);
            yS = fmaf(aS, v, omS * yS);
            float m = yF - yS;
            dG = fmaf(aG, m, omG * dG); cG *= omG;
        }
        wscan(cG, dG, lane);
        if (lane == 31) swp[2 * NW + wid] = dG;
        float uG  = __shfl_up_sync(0xffffffffu, dG, 1);
        float ucG = __shfl_up_sync(0xffffffffu, cG, 1);
        __syncthreads();
        float pG = (wid > 0) ? swp[2 * NW + wid - 1] : 0.f;
        y90 = (lane == 0) ? pG : fmaf(ucG, pG, uG);
    }
    si[tid] = yF0; si[NTH + tid] = yS0; si[2 * NTH + tid] = y90;
    __syncthreads();

    {
        int c = i0 / CHS;
        int r = i0 - c * CHS;
        float yF = si[c], yS = si[NTH + c], y9 = si[2 * NTH + c];
        int p = c * CHS;
        #pragma unroll 1
        for (int k = 0; k < 9; ++k) {
            if (k >= r) break;
            float v = sc[PADI(p + k)];
            yF = fmaf(aF, v, omF * yF);
            yS = fmaf(aS, v, omS * yS);
            float m = yF - yS;
            y9 = fmaf(aG, m, omG * y9);
        }
        float* om9 = ob + 9  * BT;
        float* osg = ob + 10 * BT;
        float* oh  = ob + 11 * BT;
        #pragma unroll
        for (int g = 0; g < CH / 4; ++g) {
            float mb[4], sb[4], hb[4];
            #pragma unroll
            for (int jj = 0; jj < 4; ++jj) {
                float v = sc[PADI(i0 + g * 4 + jj)];
                yF = fmaf(aF, v, omF * yF);
                yS = fmaf(aS, v, omS * yS);
                float m = yF - yS;
                y9 = fmaf(aG, m, omG * y9);
                mb[jj] = m; sb[jj] = y9; hb[jj] = m - y9;
            }
            *(float4*)(om9 + g * 4) = make_float4(mb[0], mb[1], mb[2], mb[3]);
            *(float4*)(osg + g * 4) = make_float4(sb[0], sb[1], sb[2], sb[3]);
            *(float4*)(oh  + g * 4) = make_float4(hb[0], hb[1], hb[2], hb[3]);
        }
    }
}

// ============ K2: window features 0-8, 12-16 (register-history) ============
struct Trk {
    float s5, s10, s50, w, wd, gs, ls, V, xprev, xm15;
};

__device__ __forceinline__ void do_group(
    float* op, size_t BT, float4 xt4,
    float4 v5, float4 v10, float4 v14, float4 v20, float4 v40,
    float2 w50a, float2 w50b, Trk& T)
{
    float xs[4]  = {xt4.x, xt4.y, xt4.z, xt4.w};
    float a5[4]  = {v5.x,  v5.y,  v5.z,  v5.w};
    float a10[4] = {v10.x, v10.y, v10.z, v10.w};
    float a14[4] = {v14.x, v14.y, v14.z, v14.w};
    float a20[4] = {v20.x, v20.y, v20.z, v20.w};
    float a40[4] = {v40.x, v40.y, v40.z, v40.w};
    float a50[4] = {w50a.x, w50a.y, w50b.x, w50b.y};
    float b0[4], b1[4], ma20[4];

    // MA5 + ratio
    #pragma unroll
    for (int k = 0; k < 4; ++k) {
        T.s5 += xs[k] - a5[k];
        b0[k] = T.s5 * 0.2f;
        b1[k] = __fdividef(xs[k], b0[k] + FEPS);
    }
    *(float4*)(op + 0 * BT) = make_float4(b0[0], b0[1], b0[2], b0[3]);
    *(float4*)(op + 1 * BT) = make_float4(b1[0], b1[1], b1[2], b1[3]);
    // MA10 + ratio
    #pragma unroll
    for (int k = 0; k < 4; ++k) {
        T.s10 += xs[k] - a10[k];
        b0[k] = T.s10 * 0.1f;
        b1[k] = __fdividef(xs[k], b0[k] + FEPS);
    }
    *(float4*)(op + 2 * BT) = make_float4(b0[0], b0[1], b0[2], b0[3]);
    *(float4*)(op + 3 * BT) = make_float4(b1[0], b1[1], b1[2], b1[3]);
    // MA20 + ratio (shared with Bollinger mid)
    #pragma unroll
    for (int k = 0; k < 4; ++k) {
        T.w += xs[k] - a20[k];
        ma20[k] = T.w * 0.05f;
        b1[k] = __fdividef(xs[k], ma20[k] + FEPS);
    }
    *(float4*)(op + 4 * BT) = make_float4(ma20[0], ma20[1], ma20[2], ma20[3]);
    *(float4*)(op + 5 * BT) = make_float4(b1[0], b1[1], b1[2], b1[3]);
    // MA50 + ratio
    #pragma unroll
    for (int k = 0; k < 4; ++k) {
        T.s50 += xs[k] - a50[k];
        b0[k] = T.s50 * 0.02f;
        b1[k] = __fdividef(xs[k], b0[k] + FEPS);
    }
    *(float4*)(op + 6 * BT) = make_float4(b0[0], b0[1], b0[2], b0[3]);
    *(float4*)(op + 7 * BT) = make_float4(b1[0], b1[1], b1[2], b1[3]);
    // RSI + ATR
    #pragma unroll
    for (int k = 0; k < 4; ++k) {
        float d = xs[k] - T.xprev;
        T.gs += fmaxf(d, 0.f);
        T.ls += fmaxf(-d, 0.f);
        float dl = a14[k] - T.xm15;
        T.gs -= fmaxf(dl, 0.f);
        T.ls -= fmaxf(-dl, 0.f);
        T.xm15 = a14[k]; T.xprev = xs[k];
        b0[k] = 100.f * __fdividef(T.gs, T.gs + T.ls + 14.f * FEPS);
        b1[k] = (T.gs + T.ls) * (1.f / 14.f);
    }
    *(float4*)(op + 8  * BT) = make_float4(b0[0], b0[1], b0[2], b0[3]);
    *(float4*)(op + 16 * BT) = make_float4(b1[0], b1[1], b1[2], b1[3]);
    // Bollinger + %B
    float b2[4], b3[4];
    #pragma unroll
    for (int k = 0; k < 4; ++k) {
        float xo = a20[k];
        T.wd += xo - a40[k];
        float mad = T.wd * 0.05f;
        float tn = xs[k] - ma20[k];
        float to = xo - mad;
        T.V += tn * tn - to * to;
        float var = fmaxf(T.V, 0.f) * 0.05f;
        float sd  = sqrtf(var + FEPS);
        float bu = ma20[k] + 2.f * sd;
        float bl = ma20[k] - 2.f * sd;
        b0[k] = bu; b1[k] = bl; b2[k] = __fdividef(xs[k] - bl, bu - bl + FEPS);
        b3[k] = ma20[k];
    }
    *(float4*)(op + 12 * BT) = make_float4(b0[0], b0[1], b0[2], b0[3]);
    *(float4*)(op + 13 * BT) = make_float4(b3[0], b3[1], b3[2], b3[3]);
    *(float4*)(op + 14 * BT) = make_float4(b1[0], b1[1], b1[2], b1[3]);
    *(float4*)(op + 15 * BT) = make_float4(b2[0], b2[1], b2[2], b2[3]);
}

extern "C" __global__ void __launch_bounds__(NTH, 4)
win_kernel(const float* __restrict__ gclose, float* __restrict__ gout, size_t BT)
{
    const int blk = blockIdx.x;
    const int row = blk >> 2;
    const int seg = blk & 3;
    const int tid = threadIdx.x;
    const float* G = gclose + (size_t)row * TT;
    const int gbase = seg * SEG + CH * tid;
    float* ob = gout + (size_t)row * TT + gbase;

    if (gbase >= 56) {
        // ---------------- fast path: register-history ----------------
        const float* P = G + gbase;
        float4 h1 = *(const float4*)(P - 4);
        float4 h2 = *(const float4*)(P - 8);
        float4 h3 = *(const float4*)(P - 12);
        float4 h4 = *(const float4*)(P - 16);
        float4 h5 = *(const float4*)(P - 20);
        float4 q1 = *(const float4*)(P - 52);
        float4 q2 = *(const float4*)(P - 48);
        float4 q3 = *(const float4*)(P - 44);
        float4 r1 = *(const float4*)(P - 40);
        float4 r2 = *(const float4*)(P - 36);
        float4 r3 = *(const float4*)(P - 32);
        float4 r4 = *(const float4*)(P - 28);
        float4 r5 = *(const float4*)(P - 24);

        Trk T;
        T.wd  = sum4(r1) + sum4(r2) + sum4(r3) + sum4(r4) + sum4(r5);   // -40..-21
        T.w   = sum4(h1) + sum4(h2) + sum4(h3) + sum4(h4) + sum4(h5);   // -20..-1
        T.s50 = q1.z + q1.w + sum4(q2) + sum4(q3) + T.wd + T.w;         // -50..-1
        T.s10 = sum4(h1) + sum4(h2) + h3.z + h3.w;                      // -10..-1
        T.s5  = sum4(h1) + h2.w;                                        // -5..-1
        // RSI init: diffs over x(-15..-1)
        T.gs = 0.f; T.ls = 0.f;
        {
            #define RSTEP(a, b) { float d = (b) - (a); T.gs += fmaxf(d, 0.f); T.ls += fmaxf(-d, 0.f); }
            RSTEP(h4.y, h4.z) RSTEP(h4.z, h4.w) RSTEP(h4.w, h3.x)
            RSTEP(h3.x, h3.y) RSTEP(h3.y, h3.z) RSTEP(h3.z, h3.w)
            RSTEP(h3.w, h2.x) RSTEP(h2.x, h2.y) RSTEP(h2.y, h2.z)
            RSTEP(h2.z, h2.w) RSTEP(h2.w, h1.x) RSTEP(h1.x, h1.y)
            RSTEP(h1.y, h1.z) RSTEP(h1.z, h1.w)
            #undef RSTEP
        }
        // Bollinger V init over j=-20..-1 (x(j)=h*, x(j-20)=r*)
        T.V = 0.f;
        {
            float wr = T.wd;
            #define VSTEP(xv, xo) { wr += (xv) - (xo); float ma = wr * 0.05f; \
                                    float tt = (xv) - ma; T.V = fmaf(tt, tt, T.V); }
            VSTEP(h5.x, r1.x) VSTEP(h5.y, r1.y) VSTEP(h5.z, r1.z) VSTEP(h5.w, r1.w)
            VSTEP(h4.x, r2.x) VSTEP(h4.y, r2.y) VSTEP(h4.z, r2.z) VSTEP(h4.w, r2.w)
            VSTEP(h3.x, r3.x) VSTEP(h3.y, r3.y) VSTEP(h3.z, r3.z) VSTEP(h3.w, r3.w)
            VSTEP(h2.x, r4.x) VSTEP(h2.y, r4.y) VSTEP(h2.z, r4.z) VSTEP(h2.w, r4.w)
            VSTEP(h1.x, r5.x) VSTEP(h1.y, r5.y) VSTEP(h1.z, r5.z) VSTEP(h1.w, r5.w)
            #undef VSTEP
        }
        T.xprev = h1.w;
        T.xm15  = h4.y;

        float4 xt0 = *(const float4*)(P);
        do_group(ob, BT, xt0,
                 make_float4(h2.w, h1.x, h1.y, h1.z),   // x(t-5)
                 make_float4(h3.z, h3.w, h2.x, h2.y),   // x(t-10)
                 make_float4(h4.z, h4.w, h3.x, h3.y),   // x(t-14)
                 h5,                                    // x(t-20)
                 r1,                                    // x(t-40)
                 make_float2(q1.z, q1.w), make_float2(q2.x, q2.y),  // x(t-50)
                 T);
        float4 xt1 = *(const float4*)(P + 4);
        do_group(ob + 4, BT, xt1,
                 make_float4(h1.w, xt0.x, xt0.y, xt0.z),
                 make_float4(h2.z, h2.w, h1.x, h1.y),
                 make_float4(h3.z, h3.w, h2.x, h2.y),
                 h4,
                 r2,
                 make_float2(q2.z, q2.w), make_float2(q3.x, q3.y),
                 T);
    } else {
        // ---------------- slow path: first 7 threads of seg-0 blocks ----------------
        #pragma unroll 1
        for (int k = 0; k < CH; ++k) {
            int t = gbase + k;
            float xt = G[t];
            float s5 = 0.f, s10 = 0.f, s20 = 0.f, s50 = 0.f;
            #pragma unroll 1
            for (int i = 0; i < 50; ++i) {
                float v = G[max(t - i, 0)];
                s50 += v;
                if (i < 20) s20 += v;
                if (i < 10) s10 += v;
                if (i < 5)  s5  += v;
            }
            float ma5 = s5 * 0.2f, ma10 = s10 * 0.1f, ma20 = s20 * 0.05f, ma50 = s50 * 0.02f;
            ob[0 * BT + k] = ma5;  ob[1 * BT + k] = __fdividef(xt, ma5  + FEPS);
            ob[2 * BT + k] = ma10; ob[3 * BT + k] = __fdividef(xt, ma10 + FEPS);
            ob[4 * BT + k] = ma20; ob[5 * BT + k] = __fdividef(xt, ma20 + FEPS);
            ob[6 * BT + k] = ma50; ob[7 * BT + k] = __fdividef(xt, ma50 + FEPS);
            float gs = 0.f, ls = 0.f;
            #pragma unroll 1
            for (int j = t - 13; j <= t; ++j) {
                float d = G[max(j, 0)] - G[max(j - 1, 0)];
                gs += fmaxf(d, 0.f);
                ls += fmaxf(-d, 0.f);
            }
            ob[8  * BT + k] = 100.f * __fdividef(gs, gs + ls + 14.f * FEPS);
            ob[16 * BT + k] = (gs + ls) * (1.f / 14.f);
            // Bollinger: rolling 20-sum for ma(j)
            float sj = 0.f;
            #pragma unroll 1
            for (int i = 0; i < 20; ++i) sj += G[max(t - 19 - 1 - i, 0)];   // sum ending t-20
            float V = 0.f;
            #pragma unroll 1
            for (int j = t - 19; j <= t; ++j) {
                sj += G[max(j, 0)] - G[max(j - 20, 0)];
                float ma = sj * 0.05f;
                float dv = G[max(j, 0)] - ma;
                V = fmaf(dv, dv, V);
            }
            float var = V * 0.05f;
            float sd = sqrtf(var + FEPS);
            float bu = ma20 + 2.f * sd, bl = ma20 - 2.f * sd;
            ob[12 * BT + k] = bu;
            ob[13 * BT + k] = ma20;
            ob[14 * BT + k] = bl;
            ob[15 * BT + k] = __fdividef(xt - bl, bu - bl + FEPS);
        }
    }
}

extern "C" void kernel_launch(void* const* d_in, const int* in_sizes, int n_in,
                              void* d_out, int out_size)
{
    const float* close = (const float*)d_in[0];
    float* out = (float*)d_out;
    int B = in_sizes[0] / TT;                 // 512
    size_t BT = (size_t)B * TT;
    win_kernel<<<B * 4, NTH>>>(close, out, BT);
    ema_kernel<<<B * 4, NTH>>>(close, out, BT);
}

// round 9
// speedup vs baseline: 1.2987x; 1.2987x over previous
#include <cuda_runtime.h>

#define TT    8192
#define SEG   2048
#define NTH   256
#define CH    8
#define NW    (NTH/32)
#define FEPS  1e-8f

#define HALO1 256
#define TOT1  (SEG + HALO1)        // 2304
#define CHS   9                    // TOT1/NTH
#define SC1   (TOT1 + TOT1/32)     // 2376

__device__ __forceinline__ int PADI(int i){ return i + (i >> 5); }
__device__ __forceinline__ float sum4(float4 v){ return (v.x + v.y) + (v.z + v.w); }

__device__ __forceinline__ void wscan(float& c, float& d, int lane){
    #pragma unroll
    for (int off = 1; off < 32; off <<= 1) {
        float pc = __shfl_up_sync(0xffffffffu, c, off);
        float pd = __shfl_up_sync(0xffffffffu, d, off);
        if (lane >= off) { d = fmaf(pd, c, d); c *= pc; }
    }
}

// ======================= K1: EMA features 9,10,11 =======================
extern "C" __global__ void __launch_bounds__(NTH, 6)
ema_kernel(const float* __restrict__ gclose, float* __restrict__ gout, size_t BT)
{
    __shared__ float sc[SC1];
    __shared__ float swp[3 * NW];
    __shared__ float si[3 * NTH];

    const int blk  = blockIdx.x;
    const int row  = blk >> 2;
    const int seg  = blk & 3;
    const int tid  = threadIdx.x;
    const int lane = tid & 31;
    const int wid  = tid >> 5;
    const float* x = gclose + (size_t)row * TT;
    const int basem = seg * SEG;

    {
        const float x0 = x[0];
        #pragma unroll
        for (int j = 0; j < 3; ++j) {
            int i4 = tid + j * NTH;
            if (i4 < TOT1 / 4) {
                int gi = basem - HALO1 + i4 * 4;
                float4 v = (gi >= 0) ? *(const float4*)(x + gi)
                                     : make_float4(x0, x0, x0, x0);
                int b = i4 * 4;
                sc[PADI(b)]     = v.x;
                sc[PADI(b + 1)] = v.y;
                sc[PADI(b + 2)] = v.z;
                sc[PADI(b + 3)] = v.w;
            }
        }
    }
    __syncthreads();

    const float aF = 2.0f / 13.0f, omF = 1.0f - aF;
    const float aS = 2.0f / 27.0f, omS = 1.0f - aS;
    const float aG = 0.2f,         omG = 0.8f;

    const int i0 = HALO1 + CH * tid;
    float* ob = gout + (size_t)row * TT + basem + CH * tid;

    float yF0, yS0;
    {
        const int s0 = tid * CHS;
        float cF = 1.f, dF = 0.f, cS = 1.f, dS = 0.f;
        #pragma unroll
        for (int k = 0; k < CHS; ++k) {
            float v = sc[PADI(s0 + k)];
            dF = fmaf(aF, v, omF * dF); cF *= omF;
            dS = fmaf(aS, v, omS * dS); cS *= omS;
        }
        wscan(cF, dF, lane);
        wscan(cS, dS, lane);
        if (lane == 31) { swp[wid] = dF; swp[NW + wid] = dS; }
        float uF  = __shfl_up_sync(0xffffffffu, dF, 1);
        float ucF = __shfl_up_sync(0xffffffffu, cF, 1);
        float uS  = __shfl_up_sync(0xffffffffu, dS, 1);
        float ucS = __shfl_up_sync(0xffffffffu, cS, 1);
        __syncthreads();
        float pF = (wid > 0) ? swp[wid - 1]      : 0.f;
        float pS = (wid > 0) ? swp[NW + wid - 1] : 0.f;
        yF0 = (lane == 0) ? pF : fmaf(ucF, pF, uF);
        yS0 = (lane == 0) ? pS : fmaf(ucS, pS, uS);
    }

    float y90;
    {
        const int s0 = tid * CHS;
        float yF = yF0, yS = yS0, cG = 1.f, dG = 0.f;
        #pragma unroll
        for (int k = 0; k < CHS; ++k) {
            float v = sc[PADI(s0 + k)];
            yF = fmaf(aF, v, omF * yF);
            yS = fmaf(aS, v, omS * yS);
            float m = yF - yS;
            dG = fmaf(aG, m, omG * dG); cG *= omG;
        }
        wscan(cG, dG, lane);
        if (lane == 31) swp[2 * NW + wid] = dG;
        float uG  = __shfl_up_sync(0xffffffffu, dG, 1);
        float ucG = __shfl_up_sync(0xffffffffu, cG, 1);
        __syncthreads();
        float pG = (wid > 0) ? swp[2 * NW + wid - 1] : 0.f;
        y90 = (lane == 0) ? pG : fmaf(ucG, pG, uG);
    }
    si[tid] = yF0; si[NTH + tid] = yS0; si[2 * NTH + tid] = y90;
    __syncthreads();

    {
        int c = i0 / CHS;
        int r = i0 - c * CHS;
        float yF = si[c], yS = si[NTH + c], y9 = si[2 * NTH + c];
        int p = c * CHS;
        #pragma unroll 1
        for (int k = 0; k < 9; ++k) {
            if (k >= r) break;
            float v = sc[PADI(p + k)];
            yF = fmaf(aF, v, omF * yF);
            yS = fmaf(aS, v, omS * yS);
            float m = yF - yS;
            y9 = fmaf(aG, m, omG * y9);
        }
        float* om9 = ob + 9  * BT;
        float* osg = ob + 10 * BT;
        float* oh  = ob + 11 * BT;
        #pragma unroll
        for (int g = 0; g < CH / 4; ++g) {
            float mb[4], sb[4], hb[4];
            #pragma unroll
            for (int jj = 0; jj < 4; ++jj) {
                float v = sc[PADI(i0 + g * 4 + jj)];
                yF = fmaf(aF, v, omF * yF);
                yS = fmaf(aS, v, omS * yS);
                float m = yF - yS;
                y9 = fmaf(aG, m, omG * y9);
                mb[jj] = m; sb[jj] = y9; hb[jj] = m - y9;
            }
            *(float4*)(om9 + g * 4) = make_float4(mb[0], mb[1], mb[2], mb[3]);
            *(float4*)(osg + g * 4) = make_float4(sb[0], sb[1], sb[2], sb[3]);
            *(float4*)(oh  + g * 4) = make_float4(hb[0], hb[1], hb[2], hb[3]);
        }
    }
}

// ============ K2: window features 0-8, 12-16 (register-history, 128-reg budget) ============
struct Trk {
    float s5, s10, s50, w, wd, gs, ls, V, xprev, xm15;
};

__device__ __forceinline__ void do_group(
    float* op, size_t BT, float4 xt4,
    float4 v5, float4 v10, float4 v14, float4 v20, float4 v40,
    float2 w50a, float2 w50b, Trk& T)
{
    float xs[4]  = {xt4.x, xt4.y, xt4.z, xt4.w};
    float a5[4]  = {v5.x,  v5.y,  v5.z,  v5.w};
    float a10[4] = {v10.x, v10.y, v10.z, v10.w};
    float a14[4] = {v14.x, v14.y, v14.z, v14.w};
    float a20[4] = {v20.x, v20.y, v20.z, v20.w};
    float a40[4] = {v40.x, v40.y, v40.z, v40.w};
    float a50[4] = {w50a.x, w50a.y, w50b.x, w50b.y};
    float b0[4], b1[4], ma20[4];

    #pragma unroll
    for (int k = 0; k < 4; ++k) {
        T.s5 += xs[k] - a5[k];
        b0[k] = T.s5 * 0.2f;
        b1[k] = __fdividef(xs[k], b0[k] + FEPS);
    }
    *(float4*)(op + 0 * BT) = make_float4(b0[0], b0[1], b0[2], b0[3]);
    *(float4*)(op + 1 * BT) = make_float4(b1[0], b1[1], b1[2], b1[3]);
    #pragma unroll
    for (int k = 0; k < 4; ++k) {
        T.s10 += xs[k] - a10[k];
        b0[k] = T.s10 * 0.1f;
        b1[k] = __fdividef(xs[k], b0[k] + FEPS);
    }
    *(float4*)(op + 2 * BT) = make_float4(b0[0], b0[1], b0[2], b0[3]);
    *(float4*)(op + 3 * BT) = make_float4(b1[0], b1[1], b1[2], b1[3]);
    #pragma unroll
    for (int k = 0; k < 4; ++k) {
        T.w += xs[k] - a20[k];
        ma20[k] = T.w * 0.05f;
        b1[k] = __fdividef(xs[k], ma20[k] + FEPS);
    }
    *(float4*)(op + 4 * BT) = make_float4(ma20[0], ma20[1], ma20[2], ma20[3]);
    *(float4*)(op + 5 * BT) = make_float4(b1[0], b1[1], b1[2], b1[3]);
    #pragma unroll
    for (int k = 0; k < 4; ++k) {
        T.s50 += xs[k] - a50[k];
        b0[k] = T.s50 * 0.02f;
        b1[k] = __fdividef(xs[k], b0[k] + FEPS);
    }
    *(float4*)(op + 6 * BT) = make_float4(b0[0], b0[1], b0[2], b0[3]);
    *(float4*)(op + 7 * BT) = make_float4(b1[0], b1[1], b1[2], b1[3]);
    #pragma unroll
    for (int k = 0; k < 4; ++k) {
        float d = xs[k] - T.xprev;
        T.gs += fmaxf(d, 0.f);
        T.ls += fmaxf(-d, 0.f);
        float dl = a14[k] - T.xm15;
        T.gs -= fmaxf(dl, 0.f);
        T.ls -= fmaxf(-dl, 0.f);
        T.xm15 = a14[k]; T.xprev = xs[k];
        b0[k] = 100.f * __fdividef(T.gs, T.gs + T.ls + 14.f * FEPS);
        b1[k] = (T.gs + T.ls) * (1.f / 14.f);
    }
    *(float4*)(op + 8  * BT) = make_float4(b0[0], b0[1], b0[2], b0[3]);
    *(float4*)(op + 16 * BT) = make_float4(b1[0], b1[1], b1[2], b1[3]);
    float b2[4], b3[4];
    #pragma unroll
    for (int k = 0; k < 4; ++k) {
        float xo = a20[k];
        T.wd += xo - a40[k];
        float mad = T.wd * 0.05f;
        float tn = xs[k] - ma20[k];
        float to = xo - mad;
        T.V += tn * tn - to * to;
        float var = fmaxf(T.V, 0.f) * 0.05f;
        float sd  = sqrtf(var + FEPS);
        float bu = ma20[k] + 2.f * sd;
        float bl = ma20[k] - 2.f * sd;
        b0[k] = bu; b1[k] = bl; b2[k] = __fdividef(xs[k] - bl, bu - bl + FEPS);
        b3[k] = ma20[k];
    }
    *(float4*)(op + 12 * BT) = make_float4(b0[0], b0[1], b0[2], b0[3]);
    *(float4*)(op + 13 * BT) = make_float4(b3[0], b3[1], b3[2], b3[3]);
    *(float4*)(op + 14 * BT) = make_float4(b1[0], b1[1], b1[2], b1[3]);
    *(float4*)(op + 15 * BT) = make_float4(b2[0], b2[1], b2[2], b2[3]);
}

extern "C" __global__ void __launch_bounds__(NTH, 2)   // 128-reg budget: no spills
win_kernel(const float* __restrict__ gclose, float* __restrict__ gout, size_t BT)
{
    const int blk = blockIdx.x;
    const int row = blk >> 2;
    const int seg = blk & 3;
    const int tid = threadIdx.x;
    const float* G = gclose + (size_t)row * TT;
    const int gbase = seg * SEG + CH * tid;
    float* ob = gout + (size_t)row * TT + gbase;

    if (gbase >= 56) {
        const float* P = G + gbase;
        float4 h1 = *(const float4*)(P - 4);
        float4 h2 = *(const float4*)(P - 8);
        float4 h3 = *(const float4*)(P - 12);
        float4 h4 = *(const float4*)(P - 16);
        float4 h5 = *(const float4*)(P - 20);
        float4 q1 = *(const float4*)(P - 52);
        float4 q2 = *(const float4*)(P - 48);
        float4 q3 = *(const float4*)(P - 44);
        float4 r1 = *(const float4*)(P - 40);
        float4 r2 = *(const float4*)(P - 36);
        float4 r3 = *(const float4*)(P - 32);
        float4 r4 = *(const float4*)(P - 28);
        float4 r5 = *(const float4*)(P - 24);
        float4 xt0 = *(const float4*)(P);
        float4 xt1 = *(const float4*)(P + 4);

        Trk T;
        T.wd  = sum4(r1) + sum4(r2) + sum4(r3) + sum4(r4) + sum4(r5);   // -40..-21
        T.w   = sum4(h1) + sum4(h2) + sum4(h3) + sum4(h4) + sum4(h5);   // -20..-1
        T.s50 = q1.z + q1.w + sum4(q2) + sum4(q3) + T.wd + T.w;         // -50..-1
        T.s10 = sum4(h1) + sum4(h2) + h3.z + h3.w;                      // -10..-1
        T.s5  = sum4(h1) + h2.w;                                        // -5..-1
        T.gs = 0.f; T.ls = 0.f;
        {
            #define RSTEP(a, b) { float d = (b) - (a); T.gs += fmaxf(d, 0.f); T.ls += fmaxf(-d, 0.f); }
            RSTEP(h4.y, h4.z) RSTEP(h4.z, h4.w) RSTEP(h4.w, h3.x)
            RSTEP(h3.x, h3.y) RSTEP(h3.y, h3.z) RSTEP(h3.z, h3.w)
            RSTEP(h3.w, h2.x) RSTEP(h2.x, h2.y) RSTEP(h2.y, h2.z)
            RSTEP(h2.z, h2.w) RSTEP(h2.w, h1.x) RSTEP(h1.x, h1.y)
            RSTEP(h1.y, h1.z) RSTEP(h1.z, h1.w)
            #undef RSTEP
        }
        T.V = 0.f;
        {
            float wr = T.wd;
            #define VSTEP(xv, xo) { wr += (xv) - (xo); float ma = wr * 0.05f; \
                                    float tt = (xv) - ma; T.V = fmaf(tt, tt, T.V); }
            VSTEP(h5.x, r1.x) VSTEP(h5.y, r1.y) VSTEP(h5.z, r1.z) VSTEP(h5.w, r1.w)
            VSTEP(h4.x, r2.x) VSTEP(h4.y, r2.y) VSTEP(h4.z, r2.z) VSTEP(h4.w, r2.w)
            VSTEP(h3.x, r3.x) VSTEP(h3.y, r3.y) VSTEP(h3.z, r3.z) VSTEP(h3.w, r3.w)
            VSTEP(h2.x, r4.x) VSTEP(h2.y, r4.y) VSTEP(h2.z, r4.z) VSTEP(h2.w, r4.w)
            VSTEP(h1.x, r5.x) VSTEP(h1.y, r5.y) VSTEP(h1.z, r5.z) VSTEP(h1.w, r5.w)
            #undef VSTEP
        }
        T.xprev = h1.w;
        T.xm15  = h4.y;

        do_group(ob, BT, xt0,
                 make_float4(h2.w, h1.x, h1.y, h1.z),   // x(t-5)
                 make_float4(h3.z, h3.w, h2.x, h2.y),   // x(t-10)
                 make_float4(h4.z, h4.w, h3.x, h3.y),   // x(t-14)
                 h5,                                    // x(t-20)
                 r1,                                    // x(t-40)
                 make_float2(q1.z, q1.w), make_float2(q2.x, q2.y),  // x(t-50)
                 T);
        do_group(ob + 4, BT, xt1,
                 make_float4(h1.w, xt0.x, xt0.y, xt0.z),
                 make_float4(h2.z, h2.w, h1.x, h1.y),
                 make_float4(h3.z, h3.w, h2.x, h2.y),
                 h4,
                 r2,
                 make_float2(q2.z, q2.w), make_float2(q3.x, q3.y),
                 T);
    } else {
        // slow path: first 7 threads of seg-0 blocks (exact clamped reference)
        #pragma unroll 1
        for (int k = 0; k < CH; ++k) {
            int t = gbase + k;
            float xt = G[t];
            float s5 = 0.f, s10 = 0.f, s20 = 0.f, s50 = 0.f;
            #pragma unroll 1
            for (int i = 0; i < 50; ++i) {
                float v = G[max(t - i, 0)];
                s50 += v;
                if (i < 20) s20 += v;
                if (i < 10) s10 += v;
                if (i < 5)  s5  += v;
            }
            float ma5 = s5 * 0.2f, ma10 = s10 * 0.1f, ma20 = s20 * 0.05f, ma50 = s50 * 0.02f;
            ob[0 * BT + k] = ma5;  ob[1 * BT + k] = __fdividef(xt, ma5  + FEPS);
            ob[2 * BT + k] = ma10; ob[3 * BT + k] = __fdividef(xt, ma10 + FEPS);
            ob[4 * BT + k] = ma20; ob[5 * BT + k] = __fdividef(xt, ma20 + FEPS);
            ob[6 * BT + k] = ma50; ob[7 * BT + k] = __fdividef(xt, ma50 + FEPS);
            float gs = 0.f, ls = 0.f;
            #pragma unroll 1
            for (int j = t - 13; j <= t; ++j) {
                float d = G[max(j, 0)] - G[max(j - 1, 0)];
                gs += fmaxf(d, 0.f);
                ls += fmaxf(-d, 0.f);
            }
            ob[8  * BT + k] = 100.f * __fdividef(gs, gs + ls + 14.f * FEPS);
            ob[16 * BT + k] = (gs + ls) * (1.f / 14.f);
            float sj = 0.f;
            #pragma unroll 1
            for (int i = 0; i < 20; ++i) sj += G[max(t - 19 - 1 - i, 0)];   // sum ending t-20
            float V = 0.f;
            #pragma unroll 1
            for (int j = t - 19; j <= t; ++j) {
                sj += G[max(j, 0)] - G[max(j - 20, 0)];
                float ma = sj * 0.05f;
                float dv = G[max(j, 0)] - ma;
                V = fmaf(dv, dv, V);
            }
            float var = V * 0.05f;
            float sd = sqrtf(var + FEPS);
            float bu = ma20 + 2.f * sd, bl = ma20 - 2.f * sd;
            ob[12 * BT + k] = bu;
            ob[13 * BT + k] = ma20;
            ob[14 * BT + k] = bl;
            ob[15 * BT + k] = __fdividef(xt - bl, bu - bl + FEPS);
        }
    }
}

extern "C" void kernel_launch(void* const* d_in, const int* in_sizes, int n_in,
                              void* d_out, int out_size)
{
    const float* close = (const float*)d_in[0];
    float* out = (float*)d_out;
    int B = in_sizes[0] / TT;                 // 512
    size_t BT = (size_t)B * TT;
    win_kernel<<<B * 4, NTH>>>(close, out, BT);
    ema_kernel<<<B * 4, NTH>>>(close, out, BT);
}

// round 10
// speedup vs baseline: 2.2493x; 1.7319x over previous
#include <cuda_runtime.h>

#define TT    8192
#define NTH   256
#define NW    (NTH/32)
#define FEPS  1e-8f

// ---- ema kernel geometry ----
#define SEG1  2048
#define HALO1 256
#define TOT1  (SEG1 + HALO1)       // 2304
#define CHS   9                    // TOT1/NTH
#define SC1   (TOT1 + TOT1/32)     // 2376
#define CH1   8

// ---- win kernel geometry ----
#define WSEG  1024
#define WCH   4

__device__ __forceinline__ int PADI(int i){ return i + (i >> 5); }
__device__ __forceinline__ float sum4(float4 v){ return (v.x + v.y) + (v.z + v.w); }

__device__ __forceinline__ void wscan(float& c, float& d, int lane){
    #pragma unroll
    for (int off = 1; off < 32; off <<= 1) {
        float pc = __shfl_up_sync(0xffffffffu, c, off);
        float pd = __shfl_up_sync(0xffffffffu, d, off);
        if (lane >= off) { d = fmaf(pd, c, d); c *= pc; }
    }
}

// ======================= K1: EMA features 9,10,11 (proven) =======================
extern "C" __global__ void __launch_bounds__(NTH, 6)
ema_kernel(const float* __restrict__ gclose, float* __restrict__ gout, size_t BT)
{
    __shared__ float sc[SC1];
    __shared__ float swp[3 * NW];
    __shared__ float si[3 * NTH];

    const int blk  = blockIdx.x;
    const int row  = blk >> 2;
    const int seg  = blk & 3;
    const int tid  = threadIdx.x;
    const int lane = tid & 31;
    const int wid  = tid >> 5;
    const float* x = gclose + (size_t)row * TT;
    const int basem = seg * SEG1;

    {
        const float x0 = x[0];
        #pragma unroll
        for (int j = 0; j < 3; ++j) {
            int i4 = tid + j * NTH;
            if (i4 < TOT1 / 4) {
                int gi = basem - HALO1 + i4 * 4;
                float4 v = (gi >= 0) ? *(const float4*)(x + gi)
                                     : make_float4(x0, x0, x0, x0);
                int b = i4 * 4;
                sc[PADI(b)]     = v.x;
                sc[PADI(b + 1)] = v.y;
                sc[PADI(b + 2)] = v.z;
                sc[PADI(b + 3)] = v.w;
            }
        }
    }
    __syncthreads();

    const float aF = 2.0f / 13.0f, omF = 1.0f - aF;
    const float aS = 2.0f / 27.0f, omS = 1.0f - aS;
    const float aG = 0.2f,         omG = 0.8f;

    const int i0 = HALO1 + CH1 * tid;
    float* ob = gout + (size_t)row * TT + basem + CH1 * tid;

    float yF0, yS0;
    {
        const int s0 = tid * CHS;
        float cF = 1.f, dF = 0.f, cS = 1.f, dS = 0.f;
        #pragma unroll
        for (int k = 0; k < CHS; ++k) {
            float v = sc[PADI(s0 + k)];
            dF = fmaf(aF, v, omF * dF); cF *= omF;
            dS = fmaf(aS, v, omS * dS); cS *= omS;
        }
        wscan(cF, dF, lane);
        wscan(cS, dS, lane);
        if (lane == 31) { swp[wid] = dF; swp[NW + wid] = dS; }
        float uF  = __shfl_up_sync(0xffffffffu, dF, 1);
        float ucF = __shfl_up_sync(0xffffffffu, cF, 1);
        float uS  = __shfl_up_sync(0xffffffffu, dS, 1);
        float ucS = __shfl_up_sync(0xffffffffu, cS, 1);
        __syncthreads();
        float pF = (wid > 0) ? swp[wid - 1]      : 0.f;
        float pS = (wid > 0) ? swp[NW + wid - 1] : 0.f;
        yF0 = (lane == 0) ? pF : fmaf(ucF, pF, uF);
        yS0 = (lane == 0) ? pS : fmaf(ucS, pS, uS);
    }

    float y90;
    {
        const int s0 = tid * CHS;
        float yF = yF0, yS = yS0, cG = 1.f, dG = 0.f;
        #pragma unroll
        for (int k = 0; k < CHS; ++k) {
            float v = sc[PADI(s0 + k)];
            yF = fmaf(aF, v, omF * yF);
            yS = fmaf(aS, v, omS * yS);
            float m = yF - yS;
            dG = fmaf(aG, m, omG * dG); cG *= omG;
        }
        wscan(cG, dG, lane);
        if (lane == 31) swp[2 * NW + wid] = dG;
        float uG  = __shfl_up_sync(0xffffffffu, dG, 1);
        float ucG = __shfl_up_sync(0xffffffffu, cG, 1);
        __syncthreads();
        float pG = (wid > 0) ? swp[2 * NW + wid - 1] : 0.f;
        y90 = (lane == 0) ? pG : fmaf(ucG, pG, uG);
    }
    si[tid] = yF0; si[NTH + tid] = yS0; si[2 * NTH + tid] = y90;
    __syncthreads();

    {
        int c = i0 / CHS;
        int r = i0 - c * CHS;
        float yF = si[c], yS = si[NTH + c], y9 = si[2 * NTH + c];
        int p = c * CHS;
        #pragma unroll 1
        for (int k = 0; k < 9; ++k) {
            if (k >= r) break;
            float v = sc[PADI(p + k)];
            yF = fmaf(aF, v, omF * yF);
            yS = fmaf(aS, v, omS * yS);
            float m = yF - yS;
            y9 = fmaf(aG, m, omG * y9);
        }
        float* om9 = ob + 9  * BT;
        float* osg = ob + 10 * BT;
        float* oh  = ob + 11 * BT;
        #pragma unroll
        for (int g = 0; g < CH1 / 4; ++g) {
            float mb[4], sb[4], hb[4];
            #pragma unroll
            for (int jj = 0; jj < 4; ++jj) {
                float v = sc[PADI(i0 + g * 4 + jj)];
                yF = fmaf(aF, v, omF * yF);
                yS = fmaf(aS, v, omS * yS);
                float m = yF - yS;
                y9 = fmaf(aG, m, omG * y9);
                mb[jj] = m; sb[jj] = y9; hb[jj] = m - y9;
            }
            *(float4*)(om9 + g * 4) = make_float4(mb[0], mb[1], mb[2], mb[3]);
            *(float4*)(osg + g * 4) = make_float4(sb[0], sb[1], sb[2], sb[3]);
            *(float4*)(oh  + g * 4) = make_float4(hb[0], hb[1], hb[2], hb[3]);
        }
    }
}

// ======== K2: window features 0-8, 12-16 — CH=4, dense stores, no spills ========
extern "C" __global__ void __launch_bounds__(NTH, 3)
win_kernel(const float* __restrict__ gclose, float* __restrict__ gout, size_t BT)
{
    const int blk = blockIdx.x;
    const int row = blk >> 3;
    const int seg = blk & 7;
    const int tid = threadIdx.x;
    const float* G = gclose + (size_t)row * TT;
    const int gbase = seg * WSEG + WCH * tid;
    float* ob = gout + (size_t)row * TT + gbase;

    if (gbase >= 52) {
        const float* P = G + gbase;
        float4 h1  = *(const float4*)(P - 4);
        float4 h2  = *(const float4*)(P - 8);
        float4 h3  = *(const float4*)(P - 12);
        float4 h4  = *(const float4*)(P - 16);
        float4 h5  = *(const float4*)(P - 20);
        float4 r24 = *(const float4*)(P - 24);
        float4 r28 = *(const float4*)(P - 28);
        float4 r32 = *(const float4*)(P - 32);
        float4 r36 = *(const float4*)(P - 36);
        float4 r40 = *(const float4*)(P - 40);
        float4 q44 = *(const float4*)(P - 44);
        float4 q48 = *(const float4*)(P - 48);
        float4 q52 = *(const float4*)(P - 52);
        float4 xt  = *(const float4*)(P);

        // ---- window state ending at t = gbase-1 ----
        float w  = sum4(h1) + sum4(h2) + sum4(h3) + sum4(h4) + sum4(h5);      // -20..-1
        float wd = sum4(r24) + sum4(r28) + sum4(r32) + sum4(r36) + sum4(r40); // -40..-21
        float s50 = q52.z + q52.w + sum4(q48) + sum4(q44) + wd + w;           // -50..-1
        float s10 = h3.z + h3.w + sum4(h2) + sum4(h1);                        // -10..-1
        float s5  = h2.w + sum4(h1);                                          // -5..-1
        float gs = 0.f, ls = 0.f;
        {
            #define RSTEP(a, b) { float d = (b) - (a); gs += fmaxf(d, 0.f); ls += fmaxf(-d, 0.f); }
            RSTEP(h4.y, h4.z) RSTEP(h4.z, h4.w) RSTEP(h4.w, h3.x)
            RSTEP(h3.x, h3.y) RSTEP(h3.y, h3.z) RSTEP(h3.z, h3.w)
            RSTEP(h3.w, h2.x) RSTEP(h2.x, h2.y) RSTEP(h2.y, h2.z)
            RSTEP(h2.z, h2.w) RSTEP(h2.w, h1.x) RSTEP(h1.x, h1.y)
            RSTEP(h1.y, h1.z) RSTEP(h1.z, h1.w)
            #undef RSTEP
        }
        float V = 0.f;
        {
            float wr = wd;
            #define VSTEP(xv, xo) { wr += (xv) - (xo); float ma = wr * 0.05f; \
                                    float tt = (xv) - ma; V = fmaf(tt, tt, V); }
            VSTEP(h5.x, r40.x) VSTEP(h5.y, r40.y) VSTEP(h5.z, r40.z) VSTEP(h5.w, r40.w)
            VSTEP(h4.x, r36.x) VSTEP(h4.y, r36.y) VSTEP(h4.z, r36.z) VSTEP(h4.w, r36.w)
            VSTEP(h3.x, r32.x) VSTEP(h3.y, r32.y) VSTEP(h3.z, r32.z) VSTEP(h3.w, r32.w)
            VSTEP(h2.x, r28.x) VSTEP(h2.y, r28.y) VSTEP(h2.z, r28.z) VSTEP(h2.w, r28.w)
            VSTEP(h1.x, r24.x) VSTEP(h1.y, r24.y) VSTEP(h1.z, r24.z) VSTEP(h1.w, r24.w)
            #undef VSTEP
        }
        float xprev = h1.w;
        float xm15  = h4.y;

        // ---- lag vectors for the 4 emitted elements ----
        float xs[4]  = {xt.x, xt.y, xt.z, xt.w};
        float a5[4]  = {h2.w, h1.x, h1.y, h1.z};
        float a10[4] = {h3.z, h3.w, h2.x, h2.y};
        float a14[4] = {h4.z, h4.w, h3.x, h3.y};
        float a20[4] = {h5.x, h5.y, h5.z, h5.w};
        float a40[4] = {r40.x, r40.y, r40.z, r40.w};
        float a50[4] = {q52.z, q52.w, q48.x, q48.y};

        float b0[4], b1[4], ma20[4];

        #pragma unroll
        for (int k = 0; k < 4; ++k) {
            s5 += xs[k] - a5[k];
            b0[k] = s5 * 0.2f;
            b1[k] = __fdividef(xs[k], b0[k] + FEPS);
        }
        *(float4*)(ob + 0 * BT) = make_float4(b0[0], b0[1], b0[2], b0[3]);
        *(float4*)(ob + 1 * BT) = make_float4(b1[0], b1[1], b1[2], b1[3]);
        #pragma unroll
        for (int k = 0; k < 4; ++k) {
            s10 += xs[k] - a10[k];
            b0[k] = s10 * 0.1f;
            b1[k] = __fdividef(xs[k], b0[k] + FEPS);
        }
        *(float4*)(ob + 2 * BT) = make_float4(b0[0], b0[1], b0[2], b0[3]);
        *(float4*)(ob + 3 * BT) = make_float4(b1[0], b1[1], b1[2], b1[3]);
        #pragma unroll
        for (int k = 0; k < 4; ++k) {
            w += xs[k] - a20[k];
            ma20[k] = w * 0.05f;
            b1[k] = __fdividef(xs[k], ma20[k] + FEPS);
        }
        *(float4*)(ob + 4 * BT) = make_float4(ma20[0], ma20[1], ma20[2], ma20[3]);
        *(float4*)(ob + 5 * BT) = make_float4(b1[0], b1[1], b1[2], b1[3]);
        #pragma unroll
        for (int k = 0; k < 4; ++k) {
            s50 += xs[k] - a50[k];
            b0[k] = s50 * 0.02f;
            b1[k] = __fdividef(xs[k], b0[k] + FEPS);
        }
        *(float4*)(ob + 6 * BT) = make_float4(b0[0], b0[1], b0[2], b0[3]);
        *(float4*)(ob + 7 * BT) = make_float4(b1[0], b1[1], b1[2], b1[3]);
        #pragma unroll
        for (int k = 0; k < 4; ++k) {
            float d = xs[k] - xprev;
            gs += fmaxf(d, 0.f);
            ls += fmaxf(-d, 0.f);
            float dl = a14[k] - xm15;
            gs -= fmaxf(dl, 0.f);
            ls -= fmaxf(-dl, 0.f);
            xm15 = a14[k]; xprev = xs[k];
            b0[k] = 100.f * __fdividef(gs, gs + ls + 14.f * FEPS);
            b1[k] = (gs + ls) * (1.f / 14.f);
        }
        *(float4*)(ob + 8  * BT) = make_float4(b0[0], b0[1], b0[2], b0[3]);
        *(float4*)(ob + 16 * BT) = make_float4(b1[0], b1[1], b1[2], b1[3]);
        float b2[4];
        #pragma unroll
        for (int k = 0; k < 4; ++k) {
            float xo = a20[k];
            wd += xo - a40[k];
            float mad = wd * 0.05f;
            float tn = xs[k] - ma20[k];
            float to = xo - mad;
            V += tn * tn - to * to;
            float var = fmaxf(V, 0.f) * 0.05f;
            float sd  = sqrtf(var + FEPS);
            float bu = ma20[k] + 2.f * sd;
            float bl = ma20[k] - 2.f * sd;
            b0[k] = bu; b1[k] = bl;
            b2[k] = __fdividef(xs[k] - bl, bu - bl + FEPS);
        }
        *(float4*)(ob + 12 * BT) = make_float4(b0[0], b0[1], b0[2], b0[3]);
        *(float4*)(ob + 13 * BT) = make_float4(ma20[0], ma20[1], ma20[2], ma20[3]);
        *(float4*)(ob + 14 * BT) = make_float4(b1[0], b1[1], b1[2], b1[3]);
        *(float4*)(ob + 15 * BT) = make_float4(b2[0], b2[1], b2[2], b2[3]);
    } else {
        // slow path: first 13 threads of seg-0 blocks (exact clamped reference)
        #pragma unroll 1
        for (int k = 0; k < WCH; ++k) {
            int t = gbase + k;
            float xt = G[t];
            float s5 = 0.f, s10 = 0.f, s20 = 0.f, s50 = 0.f;
            #pragma unroll 1
            for (int i = 0; i < 50; ++i) {
                float v = G[max(t - i, 0)];
                s50 += v;
                if (i < 20) s20 += v;
                if (i < 10) s10 += v;
                if (i < 5)  s5  += v;
            }
            float ma5 = s5 * 0.2f, ma10 = s10 * 0.1f, ma20 = s20 * 0.05f, ma50 = s50 * 0.02f;
            ob[0 * BT + k] = ma5;  ob[1 * BT + k] = __fdividef(xt, ma5  + FEPS);
            ob[2 * BT + k] = ma10; ob[3 * BT + k] = __fdividef(xt, ma10 + FEPS);
            ob[4 * BT + k] = ma20; ob[5 * BT + k] = __fdividef(xt, ma20 + FEPS);
            ob[6 * BT + k] = ma50; ob[7 * BT + k] = __fdividef(xt, ma50 + FEPS);
            float gs = 0.f, ls = 0.f;
            #pragma unroll 1
            for (int j = t - 13; j <= t; ++j) {
                float d = G[max(j, 0)] - G[max(j - 1, 0)];
                gs += fmaxf(d, 0.f);
                ls += fmaxf(-d, 0.f);
            }
            ob[8  * BT + k] = 100.f * __fdividef(gs, gs + ls + 14.f * FEPS);
            ob[16 * BT + k] = (gs + ls) * (1.f / 14.f);
            float sj = 0.f;
            #pragma unroll 1
            for (int i = 0; i < 20; ++i) sj += G[max(t - 20 - i, 0)];   // 20-sum ending t-20
            float V = 0.f;
            #pragma unroll 1
            for (int j = t - 19; j <= t; ++j) {
                sj += G[max(j, 0)] - G[max(j - 20, 0)];
                float ma = sj * 0.05f;
                float dv = G[max(j, 0)] - ma;
                V = fmaf(dv, dv, V);
            }
            float var = V * 0.05f;
            float sd = sqrtf(var + FEPS);
            float bu = ma20 + 2.f * sd, bl = ma20 - 2.f * sd;
            ob[12 * BT + k] = bu;
            ob[13 * BT + k] = ma20;
            ob[14 * BT + k] = bl;
            ob[15 * BT + k] = __fdividef(xt - bl, bu - bl + FEPS);
        }
    }
}

extern "C" void kernel_launch(void* const* d_in, const int* in_sizes, int n_in,
                              void* d_out, int out_size)
{
    const float* close = (const float*)d_in[0];
    float* out = (float*)d_out;
    int B = in_sizes[0] / TT;                 // 512
    size_t BT = (size_t)B * TT;
    win_kernel<<<B * 8, NTH>>>(close, out, BT);
    ema_kernel<<<B * 4, NTH>>>(close, out, BT);
}

// round 11
// speedup vs baseline: 2.3010x; 1.0230x over previous
#include <cuda_runtime.h>

#define TT    8192
#define NTH   256
#define NW    (NTH/32)
#define FEPS  1e-8f

// ---- ema geometry ----
#define SEG1  2048
#define HALO1 256
#define TOT1  (SEG1 + HALO1)       // 2304
#define CHS   9                    // TOT1/NTH
#define SC1   (TOT1 + TOT1/32)     // 2376
#define CH1   8

// ---- win geometry ----
#define WSEG  1024
#define WCH   4

__device__ __forceinline__ int PADI(int i){ return i + (i >> 5); }
__device__ __forceinline__ float sum4(float4 v){ return (v.x + v.y) + (v.z + v.w); }

__device__ __forceinline__ void wscan(float& c, float& d, int lane){
    #pragma unroll
    for (int off = 1; off < 32; off <<= 1) {
        float pc = __shfl_up_sync(0xffffffffu, c, off);
        float pd = __shfl_up_sync(0xffffffffu, d, off);
        if (lane >= off) { d = fmaf(pd, c, d); c *= pc; }
    }
}

// ======================= ema body: features 9,10,11 =======================
__device__ void ema_body(int blk, const float* __restrict__ gclose,
                         float* __restrict__ gout, size_t BT)
{
    __shared__ float sc[SC1];
    __shared__ float swp[3 * NW];
    __shared__ float si[3 * NTH];

    const int row  = blk >> 2;
    const int seg  = blk & 3;
    const int tid  = threadIdx.x;
    const int lane = tid & 31;
    const int wid  = tid >> 5;
    const float* x = gclose + (size_t)row * TT;
    const int basem = seg * SEG1;

    {
        const float x0 = x[0];
        #pragma unroll
        for (int j = 0; j < 3; ++j) {
            int i4 = tid + j * NTH;
            if (i4 < TOT1 / 4) {
                int gi = basem - HALO1 + i4 * 4;
                float4 v = (gi >= 0) ? *(const float4*)(x + gi)
                                     : make_float4(x0, x0, x0, x0);
                int b = i4 * 4;
                sc[PADI(b)]     = v.x;
                sc[PADI(b + 1)] = v.y;
                sc[PADI(b + 2)] = v.z;
                sc[PADI(b + 3)] = v.w;
            }
        }
    }
    __syncthreads();

    const float aF = 2.0f / 13.0f, omF = 1.0f - aF;
    const float aS = 2.0f / 27.0f, omS = 1.0f - aS;
    const float aG = 0.2f,         omG = 0.8f;

    const int i0 = HALO1 + CH1 * tid;
    float* ob = gout + (size_t)row * TT + basem + CH1 * tid;

    float yF0, yS0;
    {
        const int s0 = tid * CHS;
        float cF = 1.f, dF = 0.f, cS = 1.f, dS = 0.f;
        #pragma unroll
        for (int k = 0; k < CHS; ++k) {
            float v = sc[PADI(s0 + k)];
            dF = fmaf(aF, v, omF * dF); cF *= omF;
            dS = fmaf(aS, v, omS * dS); cS *= omS;
        }
        wscan(cF, dF, lane);
        wscan(cS, dS, lane);
        if (lane == 31) { swp[wid] = dF; swp[NW + wid] = dS; }
        float uF  = __shfl_up_sync(0xffffffffu, dF, 1);
        float ucF = __shfl_up_sync(0xffffffffu, cF, 1);
        float uS  = __shfl_up_sync(0xffffffffu, dS, 1);
        float ucS = __shfl_up_sync(0xffffffffu, cS, 1);
        __syncthreads();
        float pF = (wid > 0) ? swp[wid - 1]      : 0.f;   // om^288 kills deeper terms
        float pS = (wid > 0) ? swp[NW + wid - 1] : 0.f;
        yF0 = (lane == 0) ? pF : fmaf(ucF, pF, uF);
        yS0 = (lane == 0) ? pS : fmaf(ucS, pS, uS);
    }

    float y90;
    {
        const int s0 = tid * CHS;
        float yF = yF0, yS = yS0, cG = 1.f, dG = 0.f;
        #pragma unroll
        for (int k = 0; k < CHS; ++k) {
            float v = sc[PADI(s0 + k)];
            yF = fmaf(aF, v, omF * yF);
            yS = fmaf(aS, v, omS * yS);
            float m = yF - yS;
            dG = fmaf(aG, m, omG * dG); cG *= omG;
        }
        wscan(cG, dG, lane);
        if (lane == 31) swp[2 * NW + wid] = dG;
        float uG  = __shfl_up_sync(0xffffffffu, dG, 1);
        float ucG = __shfl_up_sync(0xffffffffu, cG, 1);
        __syncthreads();
        float pG = (wid > 0) ? swp[2 * NW + wid - 1] : 0.f;
        y90 = (lane == 0) ? pG : fmaf(ucG, pG, uG);
    }
    si[tid] = yF0; si[NTH + tid] = yS0; si[2 * NTH + tid] = y90;
    __syncthreads();

    {
        int c = i0 / CHS;
        int r = i0 - c * CHS;
        float yF = si[c], yS = si[NTH + c], y9 = si[2 * NTH + c];
        int p = c * CHS;
        #pragma unroll 1
        for (int k = 0; k < 9; ++k) {
            if (k >= r) break;
            float v = sc[PADI(p + k)];
            yF = fmaf(aF, v, omF * yF);
            yS = fmaf(aS, v, omS * yS);
            float m = yF - yS;
            y9 = fmaf(aG, m, omG * y9);
        }
        float* om9 = ob + 9  * BT;
        float* osg = ob + 10 * BT;
        float* oh  = ob + 11 * BT;
        #pragma unroll
        for (int g = 0; g < CH1 / 4; ++g) {
            float mb[4], sb[4], hb[4];
            #pragma unroll
            for (int jj = 0; jj < 4; ++jj) {
                float v = sc[PADI(i0 + g * 4 + jj)];
                yF = fmaf(aF, v, omF * yF);
                yS = fmaf(aS, v, omS * yS);
                float m = yF - yS;
                y9 = fmaf(aG, m, omG * y9);
                mb[jj] = m; sb[jj] = y9; hb[jj] = m - y9;
            }
            *(float4*)(om9 + g * 4) = make_float4(mb[0], mb[1], mb[2], mb[3]);
            *(float4*)(osg + g * 4) = make_float4(sb[0], sb[1], sb[2], sb[3]);
            *(float4*)(oh  + g * 4) = make_float4(hb[0], hb[1], hb[2], hb[3]);
        }
    }
}

// ======== win body: features 0-8, 12-16 — CH=4, dense stores ========
__device__ void win_body(int blk, const float* __restrict__ gclose,
                         float* __restrict__ gout, size_t BT)
{
    const int row = blk >> 3;
    const int seg = blk & 7;
    const int tid = threadIdx.x;
    const float* G = gclose + (size_t)row * TT;
    const int gbase = seg * WSEG + WCH * tid;
    float* ob = gout + (size_t)row * TT + gbase;

    if (gbase >= 52) {
        const float* P = G + gbase;
        float4 h1  = *(const float4*)(P - 4);
        float4 h2  = *(const float4*)(P - 8);
        float4 h3  = *(const float4*)(P - 12);
        float4 h4  = *(const float4*)(P - 16);
        float4 h5  = *(const float4*)(P - 20);
        float4 r24 = *(const float4*)(P - 24);
        float4 r28 = *(const float4*)(P - 28);
        float4 r32 = *(const float4*)(P - 32);
        float4 r36 = *(const float4*)(P - 36);
        float4 r40 = *(const float4*)(P - 40);
        float4 q44 = *(const float4*)(P - 44);
        float4 q48 = *(const float4*)(P - 48);
        float4 q52 = *(const float4*)(P - 52);
        float4 xt  = *(const float4*)(P);

        float w  = sum4(h1) + sum4(h2) + sum4(h3) + sum4(h4) + sum4(h5);      // -20..-1
        float wd = sum4(r24) + sum4(r28) + sum4(r32) + sum4(r36) + sum4(r40); // -40..-21
        float s50 = q52.z + q52.w + sum4(q48) + sum4(q44) + wd + w;           // -50..-1
        float s10 = h3.z + h3.w + sum4(h2) + sum4(h1);                        // -10..-1
        float s5  = h2.w + sum4(h1);                                          // -5..-1
        float gs = 0.f, ls = 0.f;
        {
            #define RSTEP(a, b) { float d = (b) - (a); gs += fmaxf(d, 0.f); ls += fmaxf(-d, 0.f); }
            RSTEP(h4.y, h4.z) RSTEP(h4.z, h4.w) RSTEP(h4.w, h3.x)
            RSTEP(h3.x, h3.y) RSTEP(h3.y, h3.z) RSTEP(h3.z, h3.w)
            RSTEP(h3.w, h2.x) RSTEP(h2.x, h2.y) RSTEP(h2.y, h2.z)
            RSTEP(h2.z, h2.w) RSTEP(h2.w, h1.x) RSTEP(h1.x, h1.y)
            RSTEP(h1.y, h1.z) RSTEP(h1.z, h1.w)
            #undef RSTEP
        }
        float V = 0.f;
        {
            float wr = wd;
            #define VSTEP(xv, xo) { wr += (xv) - (xo); float ma = wr * 0.05f; \
                                    float tt = (xv) - ma; V = fmaf(tt, tt, V); }
            VSTEP(h5.x, r40.x) VSTEP(h5.y, r40.y) VSTEP(h5.z, r40.z) VSTEP(h5.w, r40.w)
            VSTEP(h4.x, r36.x) VSTEP(h4.y, r36.y) VSTEP(h4.z, r36.z) VSTEP(h4.w, r36.w)
            VSTEP(h3.x, r32.x) VSTEP(h3.y, r32.y) VSTEP(h3.z, r32.z) VSTEP(h3.w, r32.w)
            VSTEP(h2.x, r28.x) VSTEP(h2.y, r28.y) VSTEP(h2.z, r28.z) VSTEP(h2.w, r28.w)
            VSTEP(h1.x, r24.x) VSTEP(h1.y, r24.y) VSTEP(h1.z, r24.z) VSTEP(h1.w, r24.w)
            #undef VSTEP
        }
        float xprev = h1.w;
        float xm15  = h4.y;

        float xs[4]  = {xt.x, xt.y, xt.z, xt.w};
        float a5[4]  = {h2.w, h1.x, h1.y, h1.z};
        float a10[4] = {h3.z, h3.w, h2.x, h2.y};
        float a14[4] = {h4.z, h4.w, h3.x, h3.y};
        float a20[4] = {h5.x, h5.y, h5.z, h5.w};
        float a40[4] = {r40.x, r40.y, r40.z, r40.w};
        float a50[4] = {q52.z, q52.w, q48.x, q48.y};

        float b0[4], b1[4], ma20[4];

        #pragma unroll
        for (int k = 0; k < 4; ++k) {
            s5 += xs[k] - a5[k];
            b0[k] = s5 * 0.2f;
            b1[k] = __fdividef(xs[k], b0[k] + FEPS);
        }
        *(float4*)(ob + 0 * BT) = make_float4(b0[0], b0[1], b0[2], b0[3]);
        *(float4*)(ob + 1 * BT) = make_float4(b1[0], b1[1], b1[2], b1[3]);
        #pragma unroll
        for (int k = 0; k < 4; ++k) {
            s10 += xs[k] - a10[k];
            b0[k] = s10 * 0.1f;
            b1[k] = __fdividef(xs[k], b0[k] + FEPS);
        }
        *(float4*)(ob + 2 * BT) = make_float4(b0[0], b0[1], b0[2], b0[3]);
        *(float4*)(ob + 3 * BT) = make_float4(b1[0], b1[1], b1[2], b1[3]);
        #pragma unroll
        for (int k = 0; k < 4; ++k) {
            w += xs[k] - a20[k];
            ma20[k] = w * 0.05f;
            b1[k] = __fdividef(xs[k], ma20[k] + FEPS);
        }
        *(float4*)(ob + 4 * BT) = make_float4(ma20[0], ma20[1], ma20[2], ma20[3]);
        *(float4*)(ob + 5 * BT) = make_float4(b1[0], b1[1], b1[2], b1[3]);
        #pragma unroll
        for (int k = 0; k < 4; ++k) {
            s50 += xs[k] - a50[k];
            b0[k] = s50 * 0.02f;
            b1[k] = __fdividef(xs[k], b0[k] + FEPS);
        }
        *(float4*)(ob + 6 * BT) = make_float4(b0[0], b0[1], b0[2], b0[3]);
        *(float4*)(ob + 7 * BT) = make_float4(b1[0], b1[1], b1[2], b1[3]);
        #pragma unroll
        for (int k = 0; k < 4; ++k) {
            float d = xs[k] - xprev;
            gs += fmaxf(d, 0.f);
            ls += fmaxf(-d, 0.f);
            float dl = a14[k] - xm15;
            gs -= fmaxf(dl, 0.f);
            ls -= fmaxf(-dl, 0.f);
            xm15 = a14[k]; xprev = xs[k];
            b0[k] = 100.f * __fdividef(gs, gs + ls + 14.f * FEPS);
            b1[k] = (gs + ls) * (1.f / 14.f);
        }
        *(float4*)(ob + 8  * BT) = make_float4(b0[0], b0[1], b0[2], b0[3]);
        *(float4*)(ob + 16 * BT) = make_float4(b1[0], b1[1], b1[2], b1[3]);
        float b2[4];
        #pragma unroll
        for (int k = 0; k < 4; ++k) {
            float xo = a20[k];
            wd += xo - a40[k];
            float mad = wd * 0.05f;
            float tn = xs[k] - ma20[k];
            float to = xo - mad;
            V += tn * tn - to * to;
            float var = fmaxf(V, 0.f) * 0.05f;
            float sd  = sqrtf(var + FEPS);
            float bu = ma20[k] + 2.f * sd;
            float bl = ma20[k] - 2.f * sd;
            b0[k] = bu; b1[k] = bl;
            b2[k] = __fdividef(xs[k] - bl, bu - bl + FEPS);
        }
        *(float4*)(ob + 12 * BT) = make_float4(b0[0], b0[1], b0[2], b0[3]);
        *(float4*)(ob + 13 * BT) = make_float4(ma20[0], ma20[1], ma20[2], ma20[3]);
        *(float4*)(ob + 14 * BT) = make_float4(b1[0], b1[1], b1[2], b1[3]);
        *(float4*)(ob + 15 * BT) = make_float4(b2[0], b2[1], b2[2], b2[3]);
    } else {
        // slow path: first 13 threads of seg-0 blocks (exact clamped reference)
        #pragma unroll 1
        for (int k = 0; k < WCH; ++k) {
            int t = gbase + k;
            float xt = G[t];
            float s5 = 0.f, s10 = 0.f, s20 = 0.f, s50 = 0.f;
            #pragma unroll 1
            for (int i = 0; i < 50; ++i) {
                float v = G[max(t - i, 0)];
                s50 += v;
                if (i < 20) s20 += v;
                if (i < 10) s10 += v;
                if (i < 5)  s5  += v;
            }
            float ma5 = s5 * 0.2f, ma10 = s10 * 0.1f, ma20 = s20 * 0.05f, ma50 = s50 * 0.02f;
            ob[0 * BT + k] = ma5;  ob[1 * BT + k] = __fdividef(xt, ma5  + FEPS);
            ob[2 * BT + k] = ma10; ob[3 * BT + k] = __fdividef(xt, ma10 + FEPS);
            ob[4 * BT + k] = ma20; ob[5 * BT + k] = __fdividef(xt, ma20 + FEPS);
            ob[6 * BT + k] = ma50; ob[7 * BT + k] = __fdividef(xt, ma50 + FEPS);
            float gs = 0.f, ls = 0.f;
            #pragma unroll 1
            for (int j = t - 13; j <= t; ++j) {
                float d = G[max(j, 0)] - G[max(j - 1, 0)];
                gs += fmaxf(d, 0.f);
                ls += fmaxf(-d, 0.f);
            }
            ob[8  * BT + k] = 100.f * __fdividef(gs, gs + ls + 14.f * FEPS);
            ob[16 * BT + k] = (gs + ls) * (1.f / 14.f);
            float sj = 0.f;
            #pragma unroll 1
            for (int i = 0; i < 20; ++i) sj += G[max(t - 20 - i, 0)];   // 20-sum ending t-20
            float V = 0.f;
            #pragma unroll 1
            for (int j = t - 19; j <= t; ++j) {
                sj += G[max(j, 0)] - G[max(j - 20, 0)];
                float ma = sj * 0.05f;
                float dv = G[max(j, 0)] - ma;
                V = fmaf(dv, dv, V);
            }
            float var = V * 0.05f;
            float sd = sqrtf(var + FEPS);
            float bu = ma20 + 2.f * sd, bl = ma20 - 2.f * sd;
            ob[12 * BT + k] = bu;
            ob[13 * BT + k] = ma20;
            ob[14 * BT + k] = bl;
            ob[15 * BT + k] = __fdividef(xt - bl, bu - bl + FEPS);
        }
    }
}

// ================= fused heterogeneous kernel: bid%3==0 -> ema =================
extern "C" __global__ void __launch_bounds__(NTH, 3)
feat_fused(const float* __restrict__ gclose, float* __restrict__ gout, size_t BT)
{
    const int bid = blockIdx.x;
    const int q = bid / 3;
    if (bid - q * 3 == 0) {
        ema_body(q, gclose, gout, BT);          // 2048 ema blocks
    } else {
        win_body(bid - q - 1, gclose, gout, BT); // 4096 win blocks
    }
}

extern "C" void kernel_launch(void* const* d_in, const int* in_sizes, int n_in,
                              void* d_out, int out_size)
{
    const float* close = (const float*)d_in[0];
    float* out = (float*)d_out;
    int B = in_sizes[0] / TT;                 // 512
    size_t BT = (size_t)B * TT;
    feat_fused<<<B * 12, NTH>>>(close, out, BT);   // 2048 ema + 4096 win, interleaved
}

// round 12
// speedup vs baseline: 2.3745x; 1.0319x over previous
#include <cuda_runtime.h>

#define TT    8192
#define NTH   256
#define NW    (NTH/32)
#define FEPS  1e-8f

// ---- ema geometry ----
#define SEG1  2048
#define HALO1 256
#define TOT1  (SEG1 + HALO1)       // 2304
#define CHS   9                    // TOT1/NTH
#define SC1   (TOT1 + TOT1/32)     // 2376
#define CH1   8

// ---- win geometry ----
#define WSEG  1024
#define WCH   4

__device__ __forceinline__ int PADI(int i){ return i + (i >> 5); }
__device__ __forceinline__ float sum4(float4 v){ return (v.x + v.y) + (v.z + v.w); }

__device__ __forceinline__ void wscan(float& c, float& d, int lane){
    #pragma unroll
    for (int off = 1; off < 32; off <<= 1) {
        float pc = __shfl_up_sync(0xffffffffu, c, off);
        float pd = __shfl_up_sync(0xffffffffu, d, off);
        if (lane >= off) { d = fmaf(pd, c, d); c *= pc; }
    }
}

// ======================= ema body: features 9,10,11 =======================
__device__ void ema_body(int blk, const float* __restrict__ gclose,
                         float* __restrict__ gout, size_t BT)
{
    __shared__ float sc[SC1];
    __shared__ float swp[3 * NW];
    __shared__ float si[3 * NTH];

    const int row  = blk >> 2;
    const int seg  = blk & 3;
    const int tid  = threadIdx.x;
    const int lane = tid & 31;
    const int wid  = tid >> 5;
    const float* x = gclose + (size_t)row * TT;
    const int basem = seg * SEG1;

    {
        const float x0 = x[0];
        #pragma unroll
        for (int j = 0; j < 3; ++j) {
            int i4 = tid + j * NTH;
            if (i4 < TOT1 / 4) {
                int gi = basem - HALO1 + i4 * 4;
                float4 v = (gi >= 0) ? *(const float4*)(x + gi)
                                     : make_float4(x0, x0, x0, x0);
                int b = i4 * 4;
                sc[PADI(b)]     = v.x;
                sc[PADI(b + 1)] = v.y;
                sc[PADI(b + 2)] = v.z;
                sc[PADI(b + 3)] = v.w;
            }
        }
    }
    __syncthreads();

    const float aF = 2.0f / 13.0f, omF = 1.0f - aF;
    const float aS = 2.0f / 27.0f, omS = 1.0f - aS;
    const float aG = 0.2f,         omG = 0.8f;

    const int i0 = HALO1 + CH1 * tid;
    float* ob = gout + (size_t)row * TT + basem + CH1 * tid;

    float yF0, yS0;
    {
        const int s0 = tid * CHS;
        float cF = 1.f, dF = 0.f, cS = 1.f, dS = 0.f;
        #pragma unroll
        for (int k = 0; k < CHS; ++k) {
            float v = sc[PADI(s0 + k)];
            dF = fmaf(aF, v, omF * dF); cF *= omF;
            dS = fmaf(aS, v, omS * dS); cS *= omS;
        }
        wscan(cF, dF, lane);
        wscan(cS, dS, lane);
        if (lane == 31) { swp[wid] = dF; swp[NW + wid] = dS; }
        float uF  = __shfl_up_sync(0xffffffffu, dF, 1);
        float ucF = __shfl_up_sync(0xffffffffu, cF, 1);
        float uS  = __shfl_up_sync(0xffffffffu, dS, 1);
        float ucS = __shfl_up_sync(0xffffffffu, cS, 1);
        __syncthreads();
        float pF = (wid > 0) ? swp[wid - 1]      : 0.f;   // om^288 kills deeper terms
        float pS = (wid > 0) ? swp[NW + wid - 1] : 0.f;
        yF0 = (lane == 0) ? pF : fmaf(ucF, pF, uF);
        yS0 = (lane == 0) ? pS : fmaf(ucS, pS, uS);
    }

    float y90;
    {
        const int s0 = tid * CHS;
        float yF = yF0, yS = yS0, cG = 1.f, dG = 0.f;
        #pragma unroll
        for (int k = 0; k < CHS; ++k) {
            float v = sc[PADI(s0 + k)];
            yF = fmaf(aF, v, omF * yF);
            yS = fmaf(aS, v, omS * yS);
            float m = yF - yS;
            dG = fmaf(aG, m, omG * dG); cG *= omG;
        }
        wscan(cG, dG, lane);
        if (lane == 31) swp[2 * NW + wid] = dG;
        float uG  = __shfl_up_sync(0xffffffffu, dG, 1);
        float ucG = __shfl_up_sync(0xffffffffu, cG, 1);
        __syncthreads();
        float pG = (wid > 0) ? swp[2 * NW + wid - 1] : 0.f;
        y90 = (lane == 0) ? pG : fmaf(ucG, pG, uG);
    }
    si[tid] = yF0; si[NTH + tid] = yS0; si[2 * NTH + tid] = y90;
    __syncthreads();

    {
        int c = i0 / CHS;
        int r = i0 - c * CHS;
        float yF = si[c], yS = si[NTH + c], y9 = si[2 * NTH + c];
        int p = c * CHS;
        #pragma unroll 1
        for (int k = 0; k < 9; ++k) {
            if (k >= r) break;
            float v = sc[PADI(p + k)];
            yF = fmaf(aF, v, omF * yF);
            yS = fmaf(aS, v, omS * yS);
            float m = yF - yS;
            y9 = fmaf(aG, m, omG * y9);
        }
        float* om9 = ob + 9  * BT;
        float* osg = ob + 10 * BT;
        float* oh  = ob + 11 * BT;
        #pragma unroll
        for (int g = 0; g < CH1 / 4; ++g) {
            float mb[4], sb[4], hb[4];
            #pragma unroll
            for (int jj = 0; jj < 4; ++jj) {
                float v = sc[PADI(i0 + g * 4 + jj)];
                yF = fmaf(aF, v, omF * yF);
                yS = fmaf(aS, v, omS * yS);
                float m = yF - yS;
                y9 = fmaf(aG, m, omG * y9);
                mb[jj] = m; sb[jj] = y9; hb[jj] = m - y9;
            }
            *(float4*)(om9 + g * 4) = make_float4(mb[0], mb[1], mb[2], mb[3]);
            *(float4*)(osg + g * 4) = make_float4(sb[0], sb[1], sb[2], sb[3]);
            *(float4*)(oh  + g * 4) = make_float4(hb[0], hb[1], hb[2], hb[3]);
        }
    }
}

// ======== win body: features 0-8, 12-16 — CH=4, staged init, low liveness ========
__device__ void win_body(int blk, const float* __restrict__ gclose,
                         float* __restrict__ gout, size_t BT)
{
    const int row = blk >> 3;
    const int seg = blk & 7;
    const int tid = threadIdx.x;
    const float* G = gclose + (size_t)row * TT;
    const int gbase = seg * WSEG + WCH * tid;
    float* ob = gout + (size_t)row * TT + gbase;

    if (gbase >= 52) {
        const float* P = G + gbase;

        // ---- stage 1: far history (q) — consumed immediately, registers freed ----
        float s50q, a50[4];
        {
            float4 q52 = *(const float4*)(P - 52);
            float4 q48 = *(const float4*)(P - 48);
            float4 q44 = *(const float4*)(P - 44);
            a50[0] = q52.z; a50[1] = q52.w; a50[2] = q48.x; a50[3] = q48.y;
            s50q = q52.z + q52.w + sum4(q48) + sum4(q44);
        }

        // ---- stage 2: mid + near history ----
        float4 r24 = *(const float4*)(P - 24);
        float4 r28 = *(const float4*)(P - 28);
        float4 r32 = *(const float4*)(P - 32);
        float4 r36 = *(const float4*)(P - 36);
        float4 r40 = *(const float4*)(P - 40);
        float4 h1  = *(const float4*)(P - 4);
        float4 h2  = *(const float4*)(P - 8);
        float4 h3  = *(const float4*)(P - 12);
        float4 h4  = *(const float4*)(P - 16);
        float4 h5  = *(const float4*)(P - 20);
        float4 xt  = *(const float4*)(P);

        float w  = sum4(h1) + sum4(h2) + sum4(h3) + sum4(h4) + sum4(h5);      // -20..-1
        float wd = sum4(r24) + sum4(r28) + sum4(r32) + sum4(r36) + sum4(r40); // -40..-21
        float s50 = s50q + wd + w;                                            // -50..-1
        float s10 = h3.z + h3.w + sum4(h2) + sum4(h1);                        // -10..-1
        float s5  = h2.w + sum4(h1);                                          // -5..-1
        float gs = 0.f, ls = 0.f;
        {
            #define RSTEP(a, b) { float d = (b) - (a); gs += fmaxf(d, 0.f); ls += fmaxf(-d, 0.f); }
            RSTEP(h4.y, h4.z) RSTEP(h4.z, h4.w) RSTEP(h4.w, h3.x)
            RSTEP(h3.x, h3.y) RSTEP(h3.y, h3.z) RSTEP(h3.z, h3.w)
            RSTEP(h3.w, h2.x) RSTEP(h2.x, h2.y) RSTEP(h2.y, h2.z)
            RSTEP(h2.z, h2.w) RSTEP(h2.w, h1.x) RSTEP(h1.x, h1.y)
            RSTEP(h1.y, h1.z) RSTEP(h1.z, h1.w)
            #undef RSTEP
        }
        float V = 0.f;
        {
            float wr = wd;
            #define VSTEP(xv, xo) { wr += (xv) - (xo); float ma = wr * 0.05f; \
                                    float tt = (xv) - ma; V = fmaf(tt, tt, V); }
            VSTEP(h5.x, r40.x) VSTEP(h5.y, r40.y) VSTEP(h5.z, r40.z) VSTEP(h5.w, r40.w)
            VSTEP(h4.x, r36.x) VSTEP(h4.y, r36.y) VSTEP(h4.z, r36.z) VSTEP(h4.w, r36.w)
            VSTEP(h3.x, r32.x) VSTEP(h3.y, r32.y) VSTEP(h3.z, r32.z) VSTEP(h3.w, r32.w)
            VSTEP(h2.x, r28.x) VSTEP(h2.y, r28.y) VSTEP(h2.z, r28.z) VSTEP(h2.w, r28.w)
            VSTEP(h1.x, r24.x) VSTEP(h1.y, r24.y) VSTEP(h1.z, r24.z) VSTEP(h1.w, r24.w)
            #undef VSTEP
        }
        float xprev = h1.w;
        float xm15  = h4.y;

        // lag vectors (r24..r36 die here; only a40 survives from r-stage)
        float xs[4]  = {xt.x, xt.y, xt.z, xt.w};
        float a5[4]  = {h2.w, h1.x, h1.y, h1.z};
        float a10[4] = {h3.z, h3.w, h2.x, h2.y};
        float a14[4] = {h4.z, h4.w, h3.x, h3.y};
        float a20[4] = {h5.x, h5.y, h5.z, h5.w};
        float a40[4] = {r40.x, r40.y, r40.z, r40.w};

        float b0[4], b1[4], ma20[4];

        #pragma unroll
        for (int k = 0; k < 4; ++k) {
            s5 += xs[k] - a5[k];
            b0[k] = s5 * 0.2f;
            b1[k] = __fdividef(xs[k], b0[k] + FEPS);
        }
        *(float4*)(ob + 0 * BT) = make_float4(b0[0], b0[1], b0[2], b0[3]);
        *(float4*)(ob + 1 * BT) = make_float4(b1[0], b1[1], b1[2], b1[3]);
        #pragma unroll
        for (int k = 0; k < 4; ++k) {
            s10 += xs[k] - a10[k];
            b0[k] = s10 * 0.1f;
            b1[k] = __fdividef(xs[k], b0[k] + FEPS);
        }
        *(float4*)(ob + 2 * BT) = make_float4(b0[0], b0[1], b0[2], b0[3]);
        *(float4*)(ob + 3 * BT) = make_float4(b1[0], b1[1], b1[2], b1[3]);
        #pragma unroll
        for (int k = 0; k < 4; ++k) {
            w += xs[k] - a20[k];
            ma20[k] = w * 0.05f;
            b1[k] = __fdividef(xs[k], ma20[k] + FEPS);
        }
        *(float4*)(ob + 4 * BT) = make_float4(ma20[0], ma20[1], ma20[2], ma20[3]);
        *(float4*)(ob + 5 * BT) = make_float4(b1[0], b1[1], b1[2], b1[3]);
        #pragma unroll
        for (int k = 0; k < 4; ++k) {
            s50 += xs[k] - a50[k];
            b0[k] = s50 * 0.02f;
            b1[k] = __fdividef(xs[k], b0[k] + FEPS);
        }
        *(float4*)(ob + 6 * BT) = make_float4(b0[0], b0[1], b0[2], b0[3]);
        *(float4*)(ob + 7 * BT) = make_float4(b1[0], b1[1], b1[2], b1[3]);
        #pragma unroll
        for (int k = 0; k < 4; ++k) {
            float d = xs[k] - xprev;
            gs += fmaxf(d, 0.f);
            ls += fmaxf(-d, 0.f);
            float dl = a14[k] - xm15;
            gs -= fmaxf(dl, 0.f);
            ls -= fmaxf(-dl, 0.f);
            xm15 = a14[k]; xprev = xs[k];
            b0[k] = 100.f * __fdividef(gs, gs + ls + 14.f * FEPS);
            b1[k] = (gs + ls) * (1.f / 14.f);
        }
        *(float4*)(ob + 8  * BT) = make_float4(b0[0], b0[1], b0[2], b0[3]);
        *(float4*)(ob + 16 * BT) = make_float4(b1[0], b1[1], b1[2], b1[3]);
        float b2[4];
        #pragma unroll
        for (int k = 0; k < 4; ++k) {
            float xo = a20[k];
            wd += xo - a40[k];
            float mad = wd * 0.05f;
            float tn = xs[k] - ma20[k];
            float to = xo - mad;
            V += tn * tn - to * to;
            float var = fmaxf(V, 0.f) * 0.05f;
            float sd  = sqrtf(var + FEPS);
            float bu = ma20[k] + 2.f * sd;
            float bl = ma20[k] - 2.f * sd;
            b0[k] = bu; b1[k] = bl;
            b2[k] = __fdividef(xs[k] - bl, bu - bl + FEPS);
        }
        *(float4*)(ob + 12 * BT) = make_float4(b0[0], b0[1], b0[2], b0[3]);
        *(float4*)(ob + 13 * BT) = make_float4(ma20[0], ma20[1], ma20[2], ma20[3]);
        *(float4*)(ob + 14 * BT) = make_float4(b1[0], b1[1], b1[2], b1[3]);
        *(float4*)(ob + 15 * BT) = make_float4(b2[0], b2[1], b2[2], b2[3]);
    } else {
        // slow path: first 13 threads of seg-0 blocks (exact clamped reference)
        #pragma unroll 1
        for (int k = 0; k < WCH; ++k) {
            int t = gbase + k;
            float xt = G[t];
            float s5 = 0.f, s10 = 0.f, s20 = 0.f, s50 = 0.f;
            #pragma unroll 1
            for (int i = 0; i < 50; ++i) {
                float v = G[max(t - i, 0)];
                s50 += v;
                if (i < 20) s20 += v;
                if (i < 10) s10 += v;
                if (i < 5)  s5  += v;
            }
            float ma5 = s5 * 0.2f, ma10 = s10 * 0.1f, ma20 = s20 * 0.05f, ma50 = s50 * 0.02f;
            ob[0 * BT + k] = ma5;  ob[1 * BT + k] = __fdividef(xt, ma5  + FEPS);
            ob[2 * BT + k] = ma10; ob[3 * BT + k] = __fdividef(xt, ma10 + FEPS);
            ob[4 * BT + k] = ma20; ob[5 * BT + k] = __fdividef(xt, ma20 + FEPS);
            ob[6 * BT + k] = ma50; ob[7 * BT + k] = __fdividef(xt, ma50 + FEPS);
            float gs = 0.f, ls = 0.f;
            #pragma unroll 1
            for (int j = t - 13; j <= t; ++j) {
                float d = G[max(j, 0)] - G[max(j - 1, 0)];
                gs += fmaxf(d, 0.f);
                ls += fmaxf(-d, 0.f);
            }
            ob[8  * BT + k] = 100.f * __fdividef(gs, gs + ls + 14.f * FEPS);
            ob[16 * BT + k] = (gs + ls) * (1.f / 14.f);
            float sj = 0.f;
            #pragma unroll 1
            for (int i = 0; i < 20; ++i) sj += G[max(t - 20 - i, 0)];   // 20-sum ending t-20
            float V = 0.f;
            #pragma unroll 1
            for (int j = t - 19; j <= t; ++j) {
                sj += G[max(j, 0)] - G[max(j - 20, 0)];
                float ma = sj * 0.05f;
                float dv = G[max(j, 0)] - ma;
                V = fmaf(dv, dv, V);
            }
            float var = V * 0.05f;
            float sd = sqrtf(var + FEPS);
            float bu = ma20 + 2.f * sd, bl = ma20 - 2.f * sd;
            ob[12 * BT + k] = bu;
            ob[13 * BT + k] = ma20;
            ob[14 * BT + k] = bl;
            ob[15 * BT + k] = __fdividef(xt - bl, bu - bl + FEPS);
        }
    }
}

// ================= fused heterogeneous kernel: bid%3==0 -> ema =================
extern "C" __global__ void __launch_bounds__(NTH, 4)
feat_fused(const float* __restrict__ gclose, float* __restrict__ gout, size_t BT)
{
    const int bid = blockIdx.x;
    const int q = bid / 3;
    if (bid - q * 3 == 0) {
        ema_body(q, gclose, gout, BT);          // 2048 ema blocks
    } else {
        win_body(bid - q - 1, gclose, gout, BT); // 4096 win blocks
    }
}

extern "C" void kernel_launch(void* const* d_in, const int* in_sizes, int n_in,
                              void* d_out, int out_size)
{
    const float* close = (const float*)d_in[0];
    float* out = (float*)d_out;
    int B = in_sizes[0] / TT;                 // 512
    size_t BT = (size_t)B * TT;
    feat_fused<<<B * 12, NTH>>>(close, out, BT);   // 2048 ema + 4096 win, interleaved
}

// round 13
// speedup vs baseline: 2.5259x; 1.0638x over previous
#include <cuda_runtime.h>

#define TT    8192
#define NTH   256
#define NW    (NTH/32)
#define FEPS  1e-8f

// ---- ema geometry (SEG=4096: halved block count, amortized scan overhead) ----
#define SEG1  4096
#define HALO1 256
#define TOT1  (SEG1 + HALO1)       // 4352
#define CHS   17                   // TOT1/NTH
#define SC1   (TOT1 + TOT1/32)     // 4488
#define CH1   16

// ---- win geometry ----
#define WSEG  1024
#define WCH   4

__device__ __forceinline__ int PADI(int i){ return i + (i >> 5); }
__device__ __forceinline__ float sum4(float4 v){ return (v.x + v.y) + (v.z + v.w); }

__device__ __forceinline__ void wscan(float& c, float& d, int lane){
    #pragma unroll
    for (int off = 1; off < 32; off <<= 1) {
        float pc = __shfl_up_sync(0xffffffffu, c, off);
        float pd = __shfl_up_sync(0xffffffffu, d, off);
        if (lane >= off) { d = fmaf(pd, c, d); c *= pc; }
    }
}

// ======================= ema body: features 9,10,11 =======================
__device__ void ema_body(int blk, const float* __restrict__ gclose,
                         float* __restrict__ gout, size_t BT)
{
    __shared__ float sc[SC1];
    __shared__ float swp[3 * NW];
    __shared__ float si[3 * NTH];

    const int row  = blk >> 1;
    const int seg  = blk & 1;
    const int tid  = threadIdx.x;
    const int lane = tid & 31;
    const int wid  = tid >> 5;
    const float* x = gclose + (size_t)row * TT;
    const int basem = seg * SEG1;

    {
        const float x0 = x[0];
        #pragma unroll
        for (int j = 0; j < 5; ++j) {
            int i4 = tid + j * NTH;
            if (i4 < TOT1 / 4) {
                int gi = basem - HALO1 + i4 * 4;
                float4 v = (gi >= 0) ? *(const float4*)(x + gi)
                                     : make_float4(x0, x0, x0, x0);
                int b = i4 * 4;
                sc[PADI(b)]     = v.x;
                sc[PADI(b + 1)] = v.y;
                sc[PADI(b + 2)] = v.z;
                sc[PADI(b + 3)] = v.w;
            }
        }
    }
    __syncthreads();

    const float aF = 2.0f / 13.0f, omF = 1.0f - aF;
    const float aS = 2.0f / 27.0f, omS = 1.0f - aS;
    const float aG = 0.2f,         omG = 0.8f;

    const int i0 = HALO1 + CH1 * tid;
    float* ob = gout + (size_t)row * TT + basem + CH1 * tid;

    // ---- register-cache the scan chunk (read once, used by pass A and B) ----
    float v[CHS];
    {
        const int s0 = tid * CHS;
        #pragma unroll
        for (int k = 0; k < CHS; ++k) v[k] = sc[PADI(s0 + k)];
    }

    // ===== pass A: EMA12/26 affine scan =====
    float yF0, yS0;
    {
        float cF = 1.f, dF = 0.f, cS = 1.f, dS = 0.f;
        #pragma unroll
        for (int k = 0; k < CHS; ++k) {
            dF = fmaf(aF, v[k], omF * dF); cF *= omF;
            dS = fmaf(aS, v[k], omS * dS); cS *= omS;
        }
        wscan(cF, dF, lane);
        wscan(cS, dS, lane);
        if (lane == 31) { swp[wid] = dF; swp[NW + wid] = dS; }
        float uF  = __shfl_up_sync(0xffffffffu, dF, 1);
        float ucF = __shfl_up_sync(0xffffffffu, cF, 1);
        float uS  = __shfl_up_sync(0xffffffffu, dS, 1);
        float ucS = __shfl_up_sync(0xffffffffu, cS, 1);
        __syncthreads();
        // per-warp decay om^544 ~ 0 -> previous warp's aggregate suffices
        float pF = (wid > 0) ? swp[wid - 1]      : 0.f;
        float pS = (wid > 0) ? swp[NW + wid - 1] : 0.f;
        yF0 = (lane == 0) ? pF : fmaf(ucF, pF, uF);
        yS0 = (lane == 0) ? pS : fmaf(ucS, pS, uS);
    }

    // ===== pass B: EMA9 over macd (zero LDS — uses register cache) =====
    float y90;
    {
        float yF = yF0, yS = yS0, cG = 1.f, dG = 0.f;
        #pragma unroll
        for (int k = 0; k < CHS; ++k) {
            yF = fmaf(aF, v[k], omF * yF);
            yS = fmaf(aS, v[k], omS * yS);
            float m = yF - yS;
            dG = fmaf(aG, m, omG * dG); cG *= omG;
        }
        wscan(cG, dG, lane);
        if (lane == 31) swp[2 * NW + wid] = dG;
        float uG  = __shfl_up_sync(0xffffffffu, dG, 1);
        float ucG = __shfl_up_sync(0xffffffffu, cG, 1);
        __syncthreads();
        float pG = (wid > 0) ? swp[2 * NW + wid - 1] : 0.f;
        y90 = (lane == 0) ? pG : fmaf(ucG, pG, uG);
    }
    si[tid] = yF0; si[NTH + tid] = yS0; si[2 * NTH + tid] = y90;
    __syncthreads();

    // ===== phase C: emit macd(9), signal(10), hist(11) =====
    {
        int c = i0 / CHS;
        int r = i0 - c * CHS;               // 0..16 replay
        float yF = si[c], yS = si[NTH + c], y9 = si[2 * NTH + c];
        int p = c * CHS;
        #pragma unroll 1
        for (int k = 0; k < CHS; ++k) {
            if (k >= r) break;
            float vv = sc[PADI(p + k)];
            yF = fmaf(aF, vv, omF * yF);
            yS = fmaf(aS, vv, omS * yS);
            float m = yF - yS;
            y9 = fmaf(aG, m, omG * y9);
        }
        float* om9 = ob + 9  * BT;
        float* osg = ob + 10 * BT;
        float* oh  = ob + 11 * BT;
        #pragma unroll
        for (int g = 0; g < CH1 / 4; ++g) {
            float mb[4], sb[4], hb[4];
            #pragma unroll
            for (int jj = 0; jj < 4; ++jj) {
                float vv = sc[PADI(i0 + g * 4 + jj)];
                yF = fmaf(aF, vv, omF * yF);
                yS = fmaf(aS, vv, omS * yS);
                float m = yF - yS;
                y9 = fmaf(aG, m, omG * y9);
                mb[jj] = m; sb[jj] = y9; hb[jj] = m - y9;
            }
            __stcs((float4*)(om9 + g * 4), make_float4(mb[0], mb[1], mb[2], mb[3]));
            __stcs((float4*)(osg + g * 4), make_float4(sb[0], sb[1], sb[2], sb[3]));
            __stcs((float4*)(oh  + g * 4), make_float4(hb[0], hb[1], hb[2], hb[3]));
        }
    }
}

// ======== win body: features 0-8, 12-16 — CH=4, staged init, low liveness ========
__device__ void win_body(int blk, const float* __restrict__ gclose,
                         float* __restrict__ gout, size_t BT)
{
    const int row = blk >> 3;
    const int seg = blk & 7;
    const int tid = threadIdx.x;
    const float* G = gclose + (size_t)row * TT;
    const int gbase = seg * WSEG + WCH * tid;
    float* ob = gout + (size_t)row * TT + gbase;

    if (gbase >= 52) {
        const float* P = G + gbase;

        // ---- stage 1: far history (q) — consumed immediately ----
        float s50q, a50[4];
        {
            float4 q52 = *(const float4*)(P - 52);
            float4 q48 = *(const float4*)(P - 48);
            float4 q44 = *(const float4*)(P - 44);
            a50[0] = q52.z; a50[1] = q52.w; a50[2] = q48.x; a50[3] = q48.y;
            s50q = q52.z + q52.w + sum4(q48) + sum4(q44);
        }

        // ---- stage 2: mid + near history ----
        float4 r24 = *(const float4*)(P - 24);
        float4 r28 = *(const float4*)(P - 28);
        float4 r32 = *(const float4*)(P - 32);
        float4 r36 = *(const float4*)(P - 36);
        float4 r40 = *(const float4*)(P - 40);
        float4 h1  = *(const float4*)(P - 4);
        float4 h2  = *(const float4*)(P - 8);
        float4 h3  = *(const float4*)(P - 12);
        float4 h4  = *(const float4*)(P - 16);
        float4 h5  = *(const float4*)(P - 20);
        float4 xt  = *(const float4*)(P);

        float w  = sum4(h1) + sum4(h2) + sum4(h3) + sum4(h4) + sum4(h5);      // -20..-1
        float wd = sum4(r24) + sum4(r28) + sum4(r32) + sum4(r36) + sum4(r40); // -40..-21
        float s50 = s50q + wd + w;                                            // -50..-1
        float s10 = h3.z + h3.w + sum4(h2) + sum4(h1);                        // -10..-1
        float s5  = h2.w + sum4(h1);                                          // -5..-1
        float gs = 0.f, ls = 0.f;
        {
            #define RSTEP(a, b) { float d = (b) - (a); gs += fmaxf(d, 0.f); ls += fmaxf(-d, 0.f); }
            RSTEP(h4.y, h4.z) RSTEP(h4.z, h4.w) RSTEP(h4.w, h3.x)
            RSTEP(h3.x, h3.y) RSTEP(h3.y, h3.z) RSTEP(h3.z, h3.w)
            RSTEP(h3.w, h2.x) RSTEP(h2.x, h2.y) RSTEP(h2.y, h2.z)
            RSTEP(h2.z, h2.w) RSTEP(h2.w, h1.x) RSTEP(h1.x, h1.y)
            RSTEP(h1.y, h1.z) RSTEP(h1.z, h1.w)
            #undef RSTEP
        }
        float V = 0.f;
        {
            float wr = wd;
            #define VSTEP(xv, xo) { wr += (xv) - (xo); float ma = wr * 0.05f; \
                                    float tt = (xv) - ma; V = fmaf(tt, tt, V); }
            VSTEP(h5.x, r40.x) VSTEP(h5.y, r40.y) VSTEP(h5.z, r40.z) VSTEP(h5.w, r40.w)
            VSTEP(h4.x, r36.x) VSTEP(h4.y, r36.y) VSTEP(h4.z, r36.z) VSTEP(h4.w, r36.w)
            VSTEP(h3.x, r32.x) VSTEP(h3.y, r32.y) VSTEP(h3.z, r32.z) VSTEP(h3.w, r32.w)
            VSTEP(h2.x, r28.x) VSTEP(h2.y, r28.y) VSTEP(h2.z, r28.z) VSTEP(h2.w, r28.w)
            VSTEP(h1.x, r24.x) VSTEP(h1.y, r24.y) VSTEP(h1.z, r24.z) VSTEP(h1.w, r24.w)
            #undef VSTEP
        }
        float xprev = h1.w;
        float xm15  = h4.y;

        float xs[4]  = {xt.x, xt.y, xt.z, xt.w};
        float a5[4]  = {h2.w, h1.x, h1.y, h1.z};
        float a10[4] = {h3.z, h3.w, h2.x, h2.y};
        float a14[4] = {h4.z, h4.w, h3.x, h3.y};
        float a20[4] = {h5.x, h5.y, h5.z, h5.w};
        float a40[4] = {r40.x, r40.y, r40.z, r40.w};

        float b0[4], b1[4], ma20[4];

        #pragma unroll
        for (int k = 0; k < 4; ++k) {
            s5 += xs[k] - a5[k];
            b0[k] = s5 * 0.2f;
            b1[k] = __fdividef(xs[k], b0[k] + FEPS);
        }
        __stcs((float4*)(ob + 0 * BT), make_float4(b0[0], b0[1], b0[2], b0[3]));
        __stcs((float4*)(ob + 1 * BT), make_float4(b1[0], b1[1], b1[2], b1[3]));
        #pragma unroll
        for (int k = 0; k < 4; ++k) {
            s10 += xs[k] - a10[k];
            b0[k] = s10 * 0.1f;
            b1[k] = __fdividef(xs[k], b0[k] + FEPS);
        }
        __stcs((float4*)(ob + 2 * BT), make_float4(b0[0], b0[1], b0[2], b0[3]));
        __stcs((float4*)(ob + 3 * BT), make_float4(b1[0], b1[1], b1[2], b1[3]));
        #pragma unroll
        for (int k = 0; k < 4; ++k) {
            w += xs[k] - a20[k];
            ma20[k] = w * 0.05f;
            b1[k] = __fdividef(xs[k], ma20[k] + FEPS);
        }
        __stcs((float4*)(ob + 4 * BT), make_float4(ma20[0], ma20[1], ma20[2], ma20[3]));
        __stcs((float4*)(ob + 5 * BT), make_float4(b1[0], b1[1], b1[2], b1[3]));
        #pragma unroll
        for (int k = 0; k < 4; ++k) {
            s50 += xs[k] - a50[k];
            b0[k] = s50 * 0.02f;
            b1[k] = __fdividef(xs[k], b0[k] + FEPS);
        }
        __stcs((float4*)(ob + 6 * BT), make_float4(b0[0], b0[1], b0[2], b0[3]));
        __stcs((float4*)(ob + 7 * BT), make_float4(b1[0], b1[1], b1[2], b1[3]));
        #pragma unroll
        for (int k = 0; k < 4; ++k) {
            float d = xs[k] - xprev;
            gs += fmaxf(d, 0.f);
            ls += fmaxf(-d, 0.f);
            float dl = a14[k] - xm15;
            gs -= fmaxf(dl, 0.f);
            ls -= fmaxf(-dl, 0.f);
            xm15 = a14[k]; xprev = xs[k];
            b0[k] = 100.f * __fdividef(gs, gs + ls + 14.f * FEPS);
            b1[k] = (gs + ls) * (1.f / 14.f);
        }
        __stcs((float4*)(ob + 8  * BT), make_float4(b0[0], b0[1], b0[2], b0[3]));
        __stcs((float4*)(ob + 16 * BT), make_float4(b1[0], b1[1], b1[2], b1[3]));
        float b2[4];
        #pragma unroll
        for (int k = 0; k < 4; ++k) {
            float xo = a20[k];
            wd += xo - a40[k];
            float mad = wd * 0.05f;
            float tn = xs[k] - ma20[k];
            float to = xo - mad;
            V += tn * tn - to * to;
            float var = fmaxf(V, 0.f) * 0.05f;
            float sd  = sqrtf(var + FEPS);
            float bu = ma20[k] + 2.f * sd;
            float bl = ma20[k] - 2.f * sd;
            b0[k] = bu; b1[k] = bl;
            b2[k] = __fdividef(xs[k] - bl, bu - bl + FEPS);
        }
        __stcs((float4*)(ob + 12 * BT), make_float4(b0[0], b0[1], b0[2], b0[3]));
        __stcs((float4*)(ob + 13 * BT), make_float4(ma20[0], ma20[1], ma20[2], ma20[3]));
        __stcs((float4*)(ob + 14 * BT), make_float4(b1[0], b1[1], b1[2], b1[3]));
        __stcs((float4*)(ob + 15 * BT), make_float4(b2[0], b2[1], b2[2], b2[3]));
    } else {
        // slow path: first 13 threads of seg-0 blocks (exact clamped reference)
        #pragma unroll 1
        for (int k = 0; k < WCH; ++k) {
            int t = gbase + k;
            float xt = G[t];
            float s5 = 0.f, s10 = 0.f, s20 = 0.f, s50 = 0.f;
            #pragma unroll 1
            for (int i = 0; i < 50; ++i) {
                float v = G[max(t - i, 0)];
                s50 += v;
                if (i < 20) s20 += v;
                if (i < 10) s10 += v;
                if (i < 5)  s5  += v;
            }
            float ma5 = s5 * 0.2f, ma10 = s10 * 0.1f, ma20 = s20 * 0.05f, ma50 = s50 * 0.02f;
            ob[0 * BT + k] = ma5;  ob[1 * BT + k] = __fdividef(xt, ma5  + FEPS);
            ob[2 * BT + k] = ma10; ob[3 * BT + k] = __fdividef(xt, ma10 + FEPS);
            ob[4 * BT + k] = ma20; ob[5 * BT + k] = __fdividef(xt, ma20 + FEPS);
            ob[6 * BT + k] = ma50; ob[7 * BT + k] = __fdividef(xt, ma50 + FEPS);
            float gs = 0.f, ls = 0.f;
            #pragma unroll 1
            for (int j = t - 13; j <= t; ++j) {
                float d = G[max(j, 0)] - G[max(j - 1, 0)];
                gs += fmaxf(d, 0.f);
                ls += fmaxf(-d, 0.f);
            }
            ob[8  * BT + k] = 100.f * __fdividef(gs, gs + ls + 14.f * FEPS);
            ob[16 * BT + k] = (gs + ls) * (1.f / 14.f);
            float sj = 0.f;
            #pragma unroll 1
            for (int i = 0; i < 20; ++i) sj += G[max(t - 20 - i, 0)];   // 20-sum ending t-20
            float V = 0.f;
            #pragma unroll 1
            for (int j = t - 19; j <= t; ++j) {
                sj += G[max(j, 0)] - G[max(j - 20, 0)];
                float ma = sj * 0.05f;
                float dv = G[max(j, 0)] - ma;
                V = fmaf(dv, dv, V);
            }
            float var = V * 0.05f;
            float sd = sqrtf(var + FEPS);
            float bu = ma20 + 2.f * sd, bl = ma20 - 2.f * sd;
            ob[12 * BT + k] = bu;
            ob[13 * BT + k] = ma20;
            ob[14 * BT + k] = bl;
            ob[15 * BT + k] = __fdividef(xt - bl, bu - bl + FEPS);
        }
    }
}

// ===== fused dispatch: 1024 ema blocks interleaved in first 4096 bids,
//       last 1024 bids are pure (short) win blocks -> no long-block tail =====
extern "C" __global__ void __launch_bounds__(NTH, 4)
feat_fused(const float* __restrict__ gclose, float* __restrict__ gout, size_t BT)
{
    const int bid = blockIdx.x;
    if (bid < 4096) {
        if ((bid & 3) == 0) ema_body(bid >> 2, gclose, gout, BT);       // 1024 ema
        else                win_body(bid - (bid >> 2) - 1, gclose, gout, BT); // 3072 win
    } else {
        win_body(bid - 1024, gclose, gout, BT);                          // 1024 win
    }
}

extern "C" void kernel_launch(void* const* d_in, const int* in_sizes, int n_in,
                              void* d_out, int out_size)
{
    const float* close = (const float*)d_in[0];
    float* out = (float*)d_out;
    int B = in_sizes[0] / TT;                 // 512
    size_t BT = (size_t)B * TT;
    feat_fused<<<B * 10, NTH>>>(close, out, BT);   // 1024 ema + 4096 win
}